// round 11
// baseline (speedup 1.0000x reference)
#include <cuda_runtime.h>
#include <cuda_bf16.h>
#include <cuda_fp16.h>
#include <cstdint>
#include <math.h>

typedef __nv_bfloat16 bf16;

// Shapes: T=64, B=64, S=64, E=1024, D=1024, G=4096
// Persistent kernel: 128 CTAs x 512 threads, one CTA per SM, 6 fast barriers/step.
// GEMM: out[n][b] split-K partials = sum_k W[n][k]*Z[b][k], 3-term hi/lo bf16 mma.sync,
// 4-stage cp.async pipeline (221KB smem) to cover DRAM latency on streamed weights.
// Attention: scores via fp32 ctxW precompute; output GEMM linearized via fp16 ctxOut:
//   attn_h = tanh( sum_s align[s]*ctxOut[s,b,:] + Wout_h . h1 ).

#define NCTA 128

// ---------------- static device scratch ----------------
__device__ __align__(16) bf16 g_Wc0_h[4096*3072], g_Wc0_l[4096*3072];  // [W_ih0 | W_hh0]
__device__ __align__(16) bf16 g_Wc1_h[4096*2048], g_Wc1_l[4096*2048];  // [W_ih1 | W_hh1]
__device__ __align__(16) bf16 g_WinT_h[1024*1024], g_WinT_l[1024*1024];// W_in^T: [e][d]
__device__ __align__(16) bf16 g_Wout_h[1024*2048], g_Wout_l[1024*2048];
__device__ __align__(16) bf16 g_embh[4096*1024],  g_embl[4096*1024];   // emb rows (t*64+b)
__device__ __align__(16) bf16 g_ctxRh[4096*1024], g_ctxRl[4096*1024];  // ctx repacked per bpair
__device__ __align__(16) bf16 g_ctxPh[4096*1024], g_ctxPl[4096*1024];  // ctx plain [(s*64+b)][d]
__device__ __align__(16) float g_ctxWT[64*64*1024];  // [(bpair*16+eblk)][srow(128)][elocal(64)]
__device__ __align__(16) float g_ctxOut[1024*64*64]; // fp32 staging [(n*64+b)][s]
__device__ __align__(16) __half g_ctxOutH[1024*64*64]; // fp16 copy read per step
__device__ __align__(16) float g_part[24*1024*64];   // split-K partials
__device__ __align__(16) bf16 g_Z0h[64*2048], g_Z0l[64*2048];  // [feed | h0_prev]
__device__ __align__(16) bf16 g_Z1h[64*2048], g_Z1l[64*2048];  // [h0_new | h1_prev]
__device__ __align__(16) bf16 g_Zoh[64*2048], g_Zol[64*2048];  // [unused | h1_new]
__device__ __align__(16) float g_h1f[64*1024];                 // fp32 h1 [b][d]
__device__ __align__(16) float g_align[64*64];                 // align [b][s]
__device__ __align__(16) float g_cT0[1024*64], g_cT1[1024*64];
__device__ __align__(16) float g_bias0[4096], g_bias1[4096];
__device__ volatile int g_arrive[NCTA];
__device__ volatile int g_release;

// ---------------- PTX helpers ----------------
__device__ __forceinline__ uint32_t smem_u32(const void* p) {
    uint32_t a;
    asm("{ .reg .u64 t; cvta.to.shared.u64 t, %1; cvt.u32.u64 %0, t; }" : "=r"(a) : "l"(p));
    return a;
}
__device__ __forceinline__ void ldm4(uint32_t* r, uint32_t a) {
    asm volatile("ldmatrix.sync.aligned.m8n8.x4.shared.b16 {%0,%1,%2,%3}, [%4];"
                 : "=r"(r[0]), "=r"(r[1]), "=r"(r[2]), "=r"(r[3]) : "r"(a));
}
__device__ __forceinline__ void mma_bf16(float* c, const uint32_t* a, uint32_t b0, uint32_t b1) {
    asm volatile("mma.sync.aligned.m16n8k16.row.col.f32.bf16.bf16.f32 "
                 "{%0,%1,%2,%3}, {%4,%5,%6,%7}, {%8,%9}, {%0,%1,%2,%3};"
                 : "+f"(c[0]), "+f"(c[1]), "+f"(c[2]), "+f"(c[3])
                 : "r"(a[0]), "r"(a[1]), "r"(a[2]), "r"(a[3]), "r"(b0), "r"(b1));
}
__device__ __forceinline__ void cpa16(uint32_t s, const void* g) {
    asm volatile("cp.async.cg.shared.global [%0], [%1], 16;" :: "r"(s), "l"(g));
}
#define CP_COMMIT() asm volatile("cp.async.commit_group;" ::: "memory")

__device__ __forceinline__ void hilo(float x, bf16& h, bf16& l) {
    h = __float2bfloat16(x);
    l = __float2bfloat16(x - __bfloat162float(h));
}

// fast global barrier: per-CTA arrive flags + CTA0 scan + release word
__device__ __forceinline__ void gsync(int& tgt, int bi) {
    __syncthreads();
    tgt++;
    if (threadIdx.x == 0) { __threadfence(); g_arrive[bi] = tgt; }
    if (bi == 0) {
        if (threadIdx.x < NCTA) {
            while (g_arrive[threadIdx.x] - tgt < 0) {}
        }
        __syncthreads();
        if (threadIdx.x == 0) { __threadfence(); g_release = tgt; }
    } else {
        if (threadIdx.x == 0) {
            while (g_release - tgt < 0) {}
            __threadfence();
        }
    }
    __syncthreads();
}

// ---------------- GEMM tile (512 threads, 4x4 warp grid, 4-stage pipeline) ----------------
static constexpr int PITCH = 72;
static constexpr int WBYTES = 128 * PITCH * 2;
static constexpr int ZBYTES = 64 * PITCH * 2;
static constexpr int BUFBYTES = 2 * WBYTES + 2 * ZBYTES;  // 55296
static constexpr int NSTAGE = 4;
static constexpr int GEMM_SMEM = NSTAGE * BUFBYTES;       // 221184

__device__ __forceinline__ void gemm_tile(
    const bf16* __restrict__ Wh, const bf16* __restrict__ Wl,
    const bf16* __restrict__ Zh, const bf16* __restrict__ Zl, int ldz,
    const bf16* __restrict__ Z2h, const bf16* __restrict__ Z2l, int ldz2, int kbound,
    float* __restrict__ out, size_t strideM, int strideB,
    int K, int n0, int k0, int chunks, char* dsm)
{
    const int tid  = threadIdx.x;
    const int lane = tid & 31, wid = tid >> 5;
    const int wm = wid >> 2, wn = wid & 3;
    const uint32_t sb = smem_u32(dsm);

    float acc[2][2][4];
#pragma unroll
    for (int mi = 0; mi < 2; mi++)
#pragma unroll
        for (int nj = 0; nj < 2; nj++)
#pragma unroll
            for (int q = 0; q < 4; q++) acc[mi][nj][q] = 0.f;

    auto stage = [&](int c) {
        const uint32_t S = sb + (c & (NSTAGE - 1)) * BUFBYTES;
        const int kb = k0 + c * 64;
#pragma unroll
        for (int i = 0; i < 2; i++) {
            int idx = i * 512 + tid;
            int row = idx >> 3, cg = idx & 7;
            size_t g = (size_t)(n0 + row) * K + kb + cg * 8;
            uint32_t d = S + (row * PITCH + cg * 8) * 2;
            cpa16(d, Wh + g);
            cpa16(d + WBYTES, Wl + g);
        }
        {
            int row = tid >> 3, cg = tid & 7;
            const bf16 *zh, *zl; size_t g;
            if (kb < kbound) {
                g = (size_t)row * ldz + kb + cg * 8;
                zh = Zh; zl = Zl;
            } else {
                g = (size_t)row * ldz2 + (kb - kbound) + cg * 8;
                zh = Z2h; zl = Z2l;
            }
            uint32_t d = S + 2 * WBYTES + (row * PITCH + cg * 8) * 2;
            cpa16(d, zh + g);
            cpa16(d + ZBYTES, zl + g);
        }
        CP_COMMIT();
    };

    // prologue: prefetch up to 3 chunks ahead
    for (int i = 0; i < NSTAGE - 1 && i < chunks; i++) stage(i);

    for (int c = 0; c < chunks; c++) {
        if (c + NSTAGE - 1 < chunks) {
            stage(c + NSTAGE - 1);
            asm volatile("cp.async.wait_group 3;" ::: "memory");
        } else {
            int rem = chunks - 1 - c;
            if (rem >= 3)      asm volatile("cp.async.wait_group 3;" ::: "memory");
            else if (rem == 2) asm volatile("cp.async.wait_group 2;" ::: "memory");
            else if (rem == 1) asm volatile("cp.async.wait_group 1;" ::: "memory");
            else               asm volatile("cp.async.wait_group 0;" ::: "memory");
        }
        __syncthreads();

        const uint32_t S = sb + (c & (NSTAGE - 1)) * BUFBYTES;
        const uint32_t aw = S + ((wm * 32 + (lane & 15)) * PITCH + (lane >> 4) * 8) * 2;
        const uint32_t bz = S + 2 * WBYTES + ((wn * 16 + (lane & 15)) * PITCH + (lane >> 4) * 8) * 2;

#pragma unroll
        for (int ks = 0; ks < 4; ks++) {
            const uint32_t koff = ks * 32;
            uint32_t ah[2][4], al[2][4], bh[4], bl[4];
#pragma unroll
            for (int mi = 0; mi < 2; mi++) {
                uint32_t a = aw + mi * 16 * PITCH * 2 + koff;
                ldm4(ah[mi], a);
                ldm4(al[mi], a + WBYTES);
            }
            ldm4(bh, bz + koff);
            ldm4(bl, bz + koff + ZBYTES);
#pragma unroll
            for (int mi = 0; mi < 2; mi++)
#pragma unroll
                for (int nj = 0; nj < 2; nj++) {
                    mma_bf16(acc[mi][nj], ah[mi], bh[nj], bh[2 + nj]);
                    mma_bf16(acc[mi][nj], ah[mi], bl[nj], bl[2 + nj]);
                    mma_bf16(acc[mi][nj], al[mi], bh[nj], bh[2 + nj]);
                }
        }
        __syncthreads();
    }

#pragma unroll
    for (int mi = 0; mi < 2; mi++)
#pragma unroll
        for (int nj = 0; nj < 2; nj++) {
            int m = n0 + wm * 32 + mi * 16 + (lane >> 2);
            int b = wn * 16 + nj * 8 + (lane & 3) * 2;
            if (strideB == 1) {
                __stcs((float2*)(out + (size_t)m * strideM + b),
                       make_float2(acc[mi][nj][0], acc[mi][nj][1]));
                __stcs((float2*)(out + (size_t)(m + 8) * strideM + b),
                       make_float2(acc[mi][nj][2], acc[mi][nj][3]));
            } else {
                out[(size_t)m * strideM + (size_t)b * strideB]           = acc[mi][nj][0];
                out[(size_t)m * strideM + (size_t)(b + 1) * strideB]     = acc[mi][nj][1];
                out[(size_t)(m + 8) * strideM + (size_t)b * strideB]     = acc[mi][nj][2];
                out[(size_t)(m + 8) * strideM + (size_t)(b + 1) * strideB] = acc[mi][nj][3];
            }
        }
}

// ---------------- cell phase ----------------
__device__ __forceinline__ void cell_phase(
    int e, const float* __restrict__ part, const float* __restrict__ bias,
    float* __restrict__ cT,
    bf16* hAh, bf16* hAl, int offA, bf16* hBh, bf16* hBl, int offB,
    float* __restrict__ h1f)
{
    int d = e >> 6, b = e & 63;
    float g[4];
#pragma unroll
    for (int j = 0; j < 4; j++) {
        float acc = bias[j * 1024 + d];
#pragma unroll
        for (int ks = 0; ks < 4; ks++)
            acc += __ldcs(part + (size_t)ks * 262144 + (size_t)j * 65536 + e);
        g[j] = acc;
    }
    float ig = 1.f / (1.f + expf(-g[0]));
    float fg = 1.f / (1.f + expf(-g[1]));
    float gg = tanhf(g[2]);
    float og = 1.f / (1.f + expf(-g[3]));
    float cn = fg * cT[e] + ig * gg;
    float h  = og * tanhf(cn);
    cT[e] = cn;
    bf16 hh, hl;
    hilo(h, hh, hl);
    hAh[b * 2048 + offA + d] = hh; hAl[b * 2048 + offA + d] = hl;
    hBh[b * 2048 + offB + d] = hh; hBl[b * 2048 + offB + d] = hl;
    if (h1f) h1f[b * 1024 + d] = h;
}

// ---------------- persistent kernel ----------------
__global__ void __launch_bounds__(512) persistent_k(
    float* __restrict__ outs, float* __restrict__ attns)
{
    extern __shared__ __align__(16) char dsm[];
    const int bi = blockIdx.x, tid = threadIdx.x;
    const int lane = tid & 31, w = tid >> 5;
    int tgt = g_release;

    for (int t = 0; t < 64; t++) {
        // ---- P1: LSTM0 GEMM: K=3072 ([emb_t | feed | h0]); 32 mtiles x 4 ks ----
        gemm_tile(g_Wc0_h, g_Wc0_l,
                  g_embh + (size_t)t * 65536, g_embl + (size_t)t * 65536, 1024,
                  g_Z0h, g_Z0l, 2048, 1024,
                  g_part + (size_t)(bi & 3) * 262144, 64, 1,
                  3072, (bi >> 2) * 128, (bi & 3) * 768, 12, dsm);
        gsync(tgt, bi);
        // ---- P2: cell0 ----
        cell_phase(bi * 512 + tid, g_part, g_bias0,
                   g_cT0, g_Z1h, g_Z1l, 0, g_Z0h, g_Z0l, 1024, nullptr);
        gsync(tgt, bi);
        // ---- P3: LSTM1 GEMM ----
        gemm_tile(g_Wc1_h, g_Wc1_l, g_Z1h, g_Z1l, 2048,
                  g_Z1h, g_Z1l, 2048, 1 << 30,
                  g_part + (size_t)(bi & 3) * 262144, 64, 1,
                  2048, (bi >> 2) * 128, (bi & 3) * 512, 8, dsm);
        gsync(tgt, bi);
        // ---- P4: cell1 (also emits fp32 h1) ----
        cell_phase(bi * 512 + tid, g_part, g_bias1,
                   g_cT1, g_Zoh, g_Zol, 1024, g_Z1h, g_Z1l, 1024, g_h1f);
        gsync(tgt, bi);
        // ---- P5: CTAs 0-63 scores+softmax; CTAs 64-127 out-GEMM h1 half ----
        if (bi < 64) {
            const int b = bi;
            float* qs = (float*)dsm;          // 1024 fp32 h1[b]
            float* sc = qs + 1024;            // 64 scores
            for (int d = tid; d < 1024; d += 512) qs[d] = g_h1f[b * 1024 + d];
            __syncthreads();
            const int bpair = b >> 1, brow = (b & 1) * 64;
#pragma unroll
            for (int so = 0; so < 4; so++) {
                int s = w * 4 + so;
                float acc = 0.f;
#pragma unroll
                for (int eblk = 0; eblk < 16; eblk++) {
                    const float* cwp = g_ctxWT +
                        ((size_t)(bpair * 16 + eblk) * 128 + brow + s) * 64;
                    acc += qs[eblk * 64 + lane] * cwp[lane];
                    acc += qs[eblk * 64 + 32 + lane] * cwp[32 + lane];
                }
#pragma unroll
                for (int off = 16; off; off >>= 1)
                    acc += __shfl_down_sync(0xffffffffu, acc, off);
                if (lane == 0) sc[s] = acc;
            }
            __syncthreads();
            if (tid < 32) {
                float v0 = sc[tid], v1 = sc[tid + 32];
                float m = fmaxf(v0, v1);
#pragma unroll
                for (int off = 16; off; off >>= 1)
                    m = fmaxf(m, __shfl_xor_sync(0xffffffffu, m, off));
                float e0 = expf(v0 - m), e1 = expf(v1 - m);
                float s = e0 + e1;
#pragma unroll
                for (int off = 16; off; off >>= 1)
                    s += __shfl_xor_sync(0xffffffffu, s, off);
                float inv = 1.f / s;
                float a0 = e0 * inv, a1 = e1 * inv;
                g_align[b * 64 + tid] = a0;
                g_align[b * 64 + tid + 32] = a1;
                float* at = attns + (size_t)t * 4096 + b * 64;
                __stcs(at + tid, a0);
                __stcs(at + tid + 32, a1);
            }
        } else {
            const int idx = bi - 64;                  // 0..63
            const int mt = idx >> 3, ks = idx & 7;    // 8 mtiles x 8 ksplits
            gemm_tile(g_Wout_h, g_Wout_l, g_Zoh, g_Zol, 2048,
                      g_Zoh, g_Zol, 2048, 1 << 30,
                      g_part + (size_t)(16 + ks) * 65536, 64, 1,
                      2048, mt * 128, 1024 + ks * 128, 2, dsm);
        }
        gsync(tgt, bi);
        // ---- P6: combine: y = sum_s align*ctxOutH + sum_ks part; tanh; outputs+feed ----
        {
            float* salign = (float*)dsm;   // 64*64
            for (int i = tid; i < 4096; i += 512) salign[i] = g_align[i];
            __syncthreads();
            int e = bi * 512 + tid;
            int n = e >> 6, b = e & 63;
            float acc = 0.f;
#pragma unroll
            for (int ks = 0; ks < 8; ks++)
                acc += __ldcs(g_part + (size_t)(16 + ks) * 65536 + e);
            const uint4* co = (const uint4*)(g_ctxOutH + (size_t)e * 64);
            const float* al = salign + b * 64;
#pragma unroll
            for (int sq = 0; sq < 8; sq++) {       // 8 x uint4 = 64 halfs
                uint4 u = co[sq];
                float2 v0 = __half22float2(*(const __half2*)&u.x);
                float2 v1 = __half22float2(*(const __half2*)&u.y);
                float2 v2 = __half22float2(*(const __half2*)&u.z);
                float2 v3 = __half22float2(*(const __half2*)&u.w);
                const float* a8 = al + sq * 8;
                acc += a8[0] * v0.x + a8[1] * v0.y + a8[2] * v1.x + a8[3] * v1.y
                     + a8[4] * v2.x + a8[5] * v2.y + a8[6] * v3.x + a8[7] * v3.y;
            }
            float h = tanhf(acc);
            __stcs(outs + (size_t)t * 65536 + b * 1024 + n, h);
            bf16 hh, hl;
            hilo(h, hh, hl);
            g_Z0h[b * 2048 + n] = hh;
            g_Z0l[b * 2048 + n] = hl;
        }
        gsync(tgt, bi);
    }
}

// ---------------- ctxW precompute: scores matrix ----------------
__global__ void __launch_bounds__(512) ctxw_pre(float* __restrict__ out)
{
    extern __shared__ __align__(16) char dsm[];
    const int bpair = blockIdx.x;   // 32
    const int eblk  = blockIdx.y;   // 16
    gemm_tile(g_ctxRh + (size_t)bpair * 131072, g_ctxRl + (size_t)bpair * 131072,
              g_WinT_h + (size_t)eblk * 65536, g_WinT_l + (size_t)eblk * 65536, 1024,
              g_WinT_h, g_WinT_l, 1024, 1 << 30,
              out + ((size_t)bpair * 16 + eblk) * 8192, 64, 1,
              1024, 0, 0, 16, dsm);
}

// ---------------- ctxOut precompute: [(n*64+b)][s] = Wout_c . ctx[s,b] ----------------
__global__ void __launch_bounds__(512) ctxout_pre(float* __restrict__ out)
{
    extern __shared__ __align__(16) char dsm[];
    const int mt = blockIdx.x;   // 8
    const int s  = blockIdx.y;   // 64
    gemm_tile(g_Wout_h, g_Wout_l,
              g_ctxPh + (size_t)s * 65536, g_ctxPl + (size_t)s * 65536, 1024,
              g_ctxPh, g_ctxPl, 1024, 1 << 30,
              out + s, 4096, 64,
              2048, mt * 128, 0, 16, dsm);
}

// ---------------- fp32 -> fp16 convert for ctxOut ----------------
__global__ void cvt_ctxout()
{
    size_t i = (size_t)blockIdx.x * blockDim.x + threadIdx.x;
    if (i < 1024ull * 64 * 64) g_ctxOutH[i] = __float2half(g_ctxOut[i]);
}

// ---------------- init state ----------------
__global__ void init_state(const float* __restrict__ input_feed,
                           const float* __restrict__ h0, const float* __restrict__ c0)
{
    int e = blockIdx.x * blockDim.x + threadIdx.x;  // 65536
    int b = e >> 10, d = e & 1023;
    bf16 hh, hl;
    hilo(input_feed[e], hh, hl);
    g_Z0h[b * 2048 + d] = hh; g_Z0l[b * 2048 + d] = hl;
    hilo(h0[e], hh, hl);
    g_Z0h[b * 2048 + 1024 + d] = hh; g_Z0l[b * 2048 + 1024 + d] = hl;
    hilo(h0[65536 + e], hh, hl);
    g_Z1h[b * 2048 + 1024 + d] = hh; g_Z1l[b * 2048 + 1024 + d] = hl;
    g_cT0[d * 64 + b] = c0[e];
    g_cT1[d * 64 + b] = c0[65536 + e];
}

// ---------------- weight prep ----------------
__global__ void prep_w(const float* __restrict__ W_ih0, const float* __restrict__ W_hh0,
                       const float* __restrict__ W_ih1, const float* __restrict__ W_hh1,
                       const float* __restrict__ W_in,  const float* __restrict__ W_out,
                       const float* __restrict__ emb,   const float* __restrict__ ctx,
                       const float* __restrict__ b_ih0, const float* __restrict__ b_hh0,
                       const float* __restrict__ b_ih1, const float* __restrict__ b_hh1)
{
    size_t stride = (size_t)gridDim.x * blockDim.x;
    for (size_t i = (size_t)blockIdx.x * blockDim.x + threadIdx.x;
         i < 4096ull * 3072ull; i += stride) {
        {   // Wc0: [W_ih0 (k<2048) | W_hh0]
            size_t n = i / 3072, k = i % 3072;
            float v = (k < 2048) ? W_ih0[n * 2048 + k] : W_hh0[n * 1024 + (k - 2048)];
            hilo(v, g_Wc0_h[i], g_Wc0_l[i]);
        }
        if (i < 4096ull * 2048ull) {
            size_t n = i >> 11, k = i & 2047;
            float v1 = (k < 1024) ? W_ih1[n * 1024 + k] : W_hh1[n * 1024 + (k - 1024)];
            hilo(v1, g_Wc1_h[i], g_Wc1_l[i]);
            if (n < 1024) hilo(W_out[i], g_Wout_h[i], g_Wout_l[i]);
        }
        if (i < 4096ull * 1024ull) {
            hilo(emb[i], g_embh[i], g_embl[i]);
            hilo(ctx[i], g_ctxPh[i], g_ctxPl[i]);
            size_t b = (i >> 10) & 63, s = i >> 16, d = i & 1023;
            size_t ri = ((b >> 1) * 128 + (b & 1) * 64 + s) * 1024 + d;
            hilo(ctx[i], g_ctxRh[ri], g_ctxRl[ri]);
        }
        if (i < 1024ull * 1024ull) {
            size_t ti = (i & 1023) * 1024 + (i >> 10);
            hilo(W_in[i], g_WinT_h[ti], g_WinT_l[ti]);
        }
        if (i < 4096) {
            g_bias0[i] = b_ih0[i] + b_hh0[i];
            g_bias1[i] = b_ih1[i] + b_hh1[i];
        }
    }
}

// ---------------- host orchestration ----------------
extern "C" void kernel_launch(void* const* d_in, const int* in_sizes, int n_in,
                              void* d_out, int out_size)
{
    (void)in_sizes; (void)n_in; (void)out_size;
    const float* emb        = (const float*)d_in[0];
    const float* context    = (const float*)d_in[1];
    const float* input_feed = (const float*)d_in[2];
    const float* h0         = (const float*)d_in[3];
    const float* c0         = (const float*)d_in[4];
    const float* W_ih0      = (const float*)d_in[5];
    const float* W_hh0      = (const float*)d_in[6];
    const float* b_ih0      = (const float*)d_in[7];
    const float* b_hh0      = (const float*)d_in[8];
    const float* W_ih1      = (const float*)d_in[9];
    const float* W_hh1      = (const float*)d_in[10];
    const float* b_ih1      = (const float*)d_in[11];
    const float* b_hh1      = (const float*)d_in[12];
    const float* W_in       = (const float*)d_in[13];
    const float* W_out      = (const float*)d_in[14];

    float* outs  = (float*)d_out;
    float* attns = outs + 64 * 64 * 1024;

    static bool attr_set = false;
    if (!attr_set) {
        cudaFuncSetAttribute(persistent_k, cudaFuncAttributeMaxDynamicSharedMemorySize, GEMM_SMEM);
        cudaFuncSetAttribute(ctxw_pre, cudaFuncAttributeMaxDynamicSharedMemorySize, GEMM_SMEM);
        cudaFuncSetAttribute(ctxout_pre, cudaFuncAttributeMaxDynamicSharedMemorySize, GEMM_SMEM);
        attr_set = true;
    }

    float *pCtxWT, *pCtxOut;
    cudaGetSymbolAddress((void**)&pCtxWT, g_ctxWT);
    cudaGetSymbolAddress((void**)&pCtxOut, g_ctxOut);

    prep_w<<<4096, 256>>>(W_ih0, W_hh0, W_ih1, W_hh1, W_in, W_out, emb, context,
                          b_ih0, b_hh0, b_ih1, b_hh1);
    init_state<<<256, 256>>>(input_feed, h0, c0);
    ctxw_pre<<<dim3(32, 16), 512, GEMM_SMEM>>>(pCtxWT);
    ctxout_pre<<<dim3(8, 64), 512, GEMM_SMEM>>>(pCtxOut);
    cvt_ctxout<<<8192, 512>>>();
    persistent_k<<<NCTA, 512, GEMM_SMEM>>>(outs, attns);
}

// round 12
// speedup vs baseline: 1.0261x; 1.0261x over previous
#include <cuda_runtime.h>
#include <cuda_bf16.h>
#include <cstdint>
#include <math.h>

typedef __nv_bfloat16 bf16;

// Shapes: T=64, B=64, S=64, E=1024, D=1024, G=4096
// Persistent kernel: 128 CTAs x 512 threads, one CTA per SM, 6 fast barriers/step.
// GEMM: out[n][b] split-K partials = sum_k W[n][k]*Z[b][k], 3-term hi/lo bf16 mma.sync,
// 2-stage pipeline with 128-wide K chunks (209KB smem) to amortize sync/staging overhead.
// embW precomputed once; attention scores via fp32 ctxW; output GEMM linearized via
// fp32 ctxOut: attn_h = tanh( sum_s align[s]*ctxOut[s,b,:] + Wout_h . h1 ).

#define NCTA 128

// ---------------- static device scratch ----------------
__device__ __align__(16) bf16 g_W0e_h[4096*1024], g_W0e_l[4096*1024];  // W_ih0[:, :1024]
__device__ __align__(16) bf16 g_Wc0_h[4096*2048], g_Wc0_l[4096*2048];  // [W_ih0[:,1024:] | W_hh0]
__device__ __align__(16) bf16 g_Wc1_h[4096*2048], g_Wc1_l[4096*2048];  // [W_ih1 | W_hh1]
__device__ __align__(16) bf16 g_WinT_h[1024*1024], g_WinT_l[1024*1024];// W_in^T: [e][d]
__device__ __align__(16) bf16 g_Wout_h[1024*2048], g_Wout_l[1024*2048];
__device__ __align__(16) bf16 g_embh[4096*1024],  g_embl[4096*1024];   // emb rows (t*64+b)
__device__ __align__(16) bf16 g_ctxRh[4096*1024], g_ctxRl[4096*1024];  // ctx repacked per bpair
__device__ __align__(16) bf16 g_ctxPh[4096*1024], g_ctxPl[4096*1024];  // ctx plain [(s*64+b)][d]
__device__ __align__(16) float g_ctxWT[64*64*1024];  // [(bpair*16+eblk)][srow(128)][elocal(64)]
__device__ __align__(16) float g_ctxOut[1024*64*64]; // [(n*64+b)][s]
__device__ __align__(16) float g_embW[64*4096*64];   // [t][n][b]
__device__ __align__(16) float g_part[24*1024*64];   // split-K partials
__device__ __align__(16) bf16 g_Z0h[64*2048], g_Z0l[64*2048];  // [feed | h0_prev]
__device__ __align__(16) bf16 g_Z1h[64*2048], g_Z1l[64*2048];  // [h0_new | h1_prev]
__device__ __align__(16) bf16 g_Zoh[64*2048], g_Zol[64*2048];  // [unused | h1_new]
__device__ __align__(16) float g_h1f[64*1024];                 // fp32 h1 [b][d]
__device__ __align__(16) float g_align[64*64];                 // align [b][s]
__device__ __align__(16) float g_cT0[1024*64], g_cT1[1024*64];
__device__ __align__(16) float g_bias0[4096], g_bias1[4096];
__device__ volatile int g_arrive[NCTA];
__device__ volatile int g_release;

// ---------------- PTX helpers ----------------
__device__ __forceinline__ uint32_t smem_u32(const void* p) {
    uint32_t a;
    asm("{ .reg .u64 t; cvta.to.shared.u64 t, %1; cvt.u32.u64 %0, t; }" : "=r"(a) : "l"(p));
    return a;
}
__device__ __forceinline__ void ldm4(uint32_t* r, uint32_t a) {
    asm volatile("ldmatrix.sync.aligned.m8n8.x4.shared.b16 {%0,%1,%2,%3}, [%4];"
                 : "=r"(r[0]), "=r"(r[1]), "=r"(r[2]), "=r"(r[3]) : "r"(a));
}
__device__ __forceinline__ void mma_bf16(float* c, const uint32_t* a, uint32_t b0, uint32_t b1) {
    asm volatile("mma.sync.aligned.m16n8k16.row.col.f32.bf16.bf16.f32 "
                 "{%0,%1,%2,%3}, {%4,%5,%6,%7}, {%8,%9}, {%0,%1,%2,%3};"
                 : "+f"(c[0]), "+f"(c[1]), "+f"(c[2]), "+f"(c[3])
                 : "r"(a[0]), "r"(a[1]), "r"(a[2]), "r"(a[3]), "r"(b0), "r"(b1));
}
__device__ __forceinline__ void cpa16(uint32_t s, const void* g) {
    asm volatile("cp.async.cg.shared.global [%0], [%1], 16;" :: "r"(s), "l"(g));
}
#define CP_COMMIT() asm volatile("cp.async.commit_group;" ::: "memory")

__device__ __forceinline__ void hilo(float x, bf16& h, bf16& l) {
    h = __float2bfloat16(x);
    l = __float2bfloat16(x - __bfloat162float(h));
}

// fast global barrier: per-CTA arrive flags + CTA0 scan + release word
__device__ __forceinline__ void gsync(int& tgt, int bi) {
    __syncthreads();
    tgt++;
    if (threadIdx.x == 0) { __threadfence(); g_arrive[bi] = tgt; }
    if (bi == 0) {
        if (threadIdx.x < NCTA) {
            while (g_arrive[threadIdx.x] - tgt < 0) {}
        }
        __syncthreads();
        if (threadIdx.x == 0) { __threadfence(); g_release = tgt; }
    } else {
        if (threadIdx.x == 0) {
            while (g_release - tgt < 0) {}
            __threadfence();
        }
    }
    __syncthreads();
}

// ---------------- GEMM tile (512 threads, 4x4 warp grid, Kchunk=128, 2 stages) ----------------
static constexpr int PITCH = 136;                   // bf16 elems; 272B rows
static constexpr int WBYTES = 128 * PITCH * 2;      // 34816
static constexpr int ZBYTES = 64 * PITCH * 2;       // 17408
static constexpr int BUFBYTES = 2 * WBYTES + 2 * ZBYTES;  // 104448
static constexpr int GEMM_SMEM = 2 * BUFBYTES;            // 208896

__device__ __forceinline__ void gemm_tile(
    const bf16* __restrict__ Wh, const bf16* __restrict__ Wl,
    const bf16* __restrict__ Zh, const bf16* __restrict__ Zl, int ldz,
    float* __restrict__ out, size_t strideM, int strideB,
    int K, int n0, int k0, int chunks, char* dsm)
{
    const int tid  = threadIdx.x;
    const int lane = tid & 31, wid = tid >> 5;
    const int wm = wid >> 2, wn = wid & 3;
    const uint32_t sb = smem_u32(dsm);

    float acc[2][2][4];
#pragma unroll
    for (int mi = 0; mi < 2; mi++)
#pragma unroll
        for (int nj = 0; nj < 2; nj++)
#pragma unroll
            for (int q = 0; q < 4; q++) acc[mi][nj][q] = 0.f;

    auto stage = [&](int c) {
        const uint32_t S = sb + (c & 1) * BUFBYTES;
        const int kb = k0 + c * 128;
#pragma unroll
        for (int i = 0; i < 4; i++) {
            int idx = i * 512 + tid;
            int row = idx >> 4, cg = idx & 15;
            size_t g = (size_t)(n0 + row) * K + kb + cg * 8;
            uint32_t d = S + (row * PITCH + cg * 8) * 2;
            cpa16(d, Wh + g);
            cpa16(d + WBYTES, Wl + g);
        }
#pragma unroll
        for (int i = 0; i < 2; i++) {
            int idx = i * 512 + tid;
            int row = idx >> 4, cg = idx & 15;
            size_t g = (size_t)row * ldz + kb + cg * 8;
            uint32_t d = S + 2 * WBYTES + (row * PITCH + cg * 8) * 2;
            cpa16(d, Zh + g);
            cpa16(d + ZBYTES, Zl + g);
        }
        CP_COMMIT();
    };

    stage(0);
    for (int c = 0; c < chunks; c++) {
        if (c + 1 < chunks) {
            stage(c + 1);
            asm volatile("cp.async.wait_group 1;" ::: "memory");
        } else {
            asm volatile("cp.async.wait_group 0;" ::: "memory");
        }
        __syncthreads();

        const uint32_t S = sb + (c & 1) * BUFBYTES;
        const uint32_t aw = S + ((wm * 32 + (lane & 15)) * PITCH + (lane >> 4) * 8) * 2;
        const uint32_t bz = S + 2 * WBYTES + ((wn * 16 + (lane & 15)) * PITCH + (lane >> 4) * 8) * 2;

#pragma unroll
        for (int ks = 0; ks < 8; ks++) {
            const uint32_t koff = ks * 32;
            uint32_t ah[2][4], al[2][4], bh[4], bl[4];
#pragma unroll
            for (int mi = 0; mi < 2; mi++) {
                uint32_t a = aw + mi * 16 * PITCH * 2 + koff;
                ldm4(ah[mi], a);
                ldm4(al[mi], a + WBYTES);
            }
            ldm4(bh, bz + koff);
            ldm4(bl, bz + koff + ZBYTES);
#pragma unroll
            for (int mi = 0; mi < 2; mi++)
#pragma unroll
                for (int nj = 0; nj < 2; nj++) {
                    mma_bf16(acc[mi][nj], ah[mi], bh[nj], bh[2 + nj]);
                    mma_bf16(acc[mi][nj], ah[mi], bl[nj], bl[2 + nj]);
                    mma_bf16(acc[mi][nj], al[mi], bh[nj], bh[2 + nj]);
                }
        }
        __syncthreads();
    }

#pragma unroll
    for (int mi = 0; mi < 2; mi++)
#pragma unroll
        for (int nj = 0; nj < 2; nj++) {
            int m = n0 + wm * 32 + mi * 16 + (lane >> 2);
            int b = wn * 16 + nj * 8 + (lane & 3) * 2;
            if (strideB == 1) {
                __stcs((float2*)(out + (size_t)m * strideM + b),
                       make_float2(acc[mi][nj][0], acc[mi][nj][1]));
                __stcs((float2*)(out + (size_t)(m + 8) * strideM + b),
                       make_float2(acc[mi][nj][2], acc[mi][nj][3]));
            } else {
                out[(size_t)m * strideM + (size_t)b * strideB]             = acc[mi][nj][0];
                out[(size_t)m * strideM + (size_t)(b + 1) * strideB]       = acc[mi][nj][1];
                out[(size_t)(m + 8) * strideM + (size_t)b * strideB]       = acc[mi][nj][2];
                out[(size_t)(m + 8) * strideM + (size_t)(b + 1) * strideB] = acc[mi][nj][3];
            }
        }
}

// ---------------- cell phase ----------------
__device__ __forceinline__ void cell_phase(
    int e, const float* __restrict__ part,
    const float* __restrict__ base, const float* __restrict__ bias,
    float* __restrict__ cT,
    bf16* hAh, bf16* hAl, int offA, bf16* hBh, bf16* hBl, int offB,
    float* __restrict__ h1f)
{
    int d = e >> 6, b = e & 63;
    float g[4];
#pragma unroll
    for (int j = 0; j < 4; j++) {
        float acc = bias[j * 1024 + d];
        if (base) acc += __ldcs(base + (size_t)j * 65536 + e);
#pragma unroll
        for (int ks = 0; ks < 4; ks++)
            acc += __ldcs(part + (size_t)ks * 262144 + (size_t)j * 65536 + e);
        g[j] = acc;
    }
    float ig = 1.f / (1.f + expf(-g[0]));
    float fg = 1.f / (1.f + expf(-g[1]));
    float gg = tanhf(g[2]);
    float og = 1.f / (1.f + expf(-g[3]));
    float cn = fg * cT[e] + ig * gg;
    float h  = og * tanhf(cn);
    cT[e] = cn;
    bf16 hh, hl;
    hilo(h, hh, hl);
    hAh[b * 2048 + offA + d] = hh; hAl[b * 2048 + offA + d] = hl;
    hBh[b * 2048 + offB + d] = hh; hBl[b * 2048 + offB + d] = hl;
    if (h1f) h1f[b * 1024 + d] = h;
}

// ---------------- persistent kernel ----------------
__global__ void __launch_bounds__(512) persistent_k(
    float* __restrict__ outs, float* __restrict__ attns)
{
    extern __shared__ __align__(16) char dsm[];
    const int bi = blockIdx.x, tid = threadIdx.x;
    const int lane = tid & 31, w = tid >> 5;
    int tgt = g_release;

    for (int t = 0; t < 64; t++) {
        // ---- P1: LSTM0 GEMM: [feed|h0] K=2048; 32 mtiles x 4 ks, 4 chunks ----
        gemm_tile(g_Wc0_h, g_Wc0_l, g_Z0h, g_Z0l, 2048,
                  g_part + (size_t)(bi & 3) * 262144, 64, 1,
                  2048, (bi >> 2) * 128, (bi & 3) * 512, 4, dsm);
        gsync(tgt, bi);
        // ---- P2: cell0 (adds precomputed embW base) ----
        cell_phase(bi * 512 + tid, g_part, g_embW + (size_t)t * 262144, g_bias0,
                   g_cT0, g_Z1h, g_Z1l, 0, g_Z0h, g_Z0l, 1024, nullptr);
        gsync(tgt, bi);
        // ---- P3: LSTM1 GEMM ----
        gemm_tile(g_Wc1_h, g_Wc1_l, g_Z1h, g_Z1l, 2048,
                  g_part + (size_t)(bi & 3) * 262144, 64, 1,
                  2048, (bi >> 2) * 128, (bi & 3) * 512, 4, dsm);
        gsync(tgt, bi);
        // ---- P4: cell1 (also emits fp32 h1) ----
        cell_phase(bi * 512 + tid, g_part, nullptr, g_bias1,
                   g_cT1, g_Zoh, g_Zol, 1024, g_Z1h, g_Z1l, 1024, g_h1f);
        gsync(tgt, bi);
        // ---- P5: CTAs 0-63 scores+softmax; CTAs 64-127 out-GEMM h1 half ----
        if (bi < 64) {
            const int b = bi;
            float* qs = (float*)dsm;          // 1024 fp32 h1[b]
            float* sc = qs + 1024;            // 64 scores
            for (int d = tid; d < 1024; d += 512) qs[d] = g_h1f[b * 1024 + d];
            __syncthreads();
            const int bpair = b >> 1, brow = (b & 1) * 64;
#pragma unroll
            for (int so = 0; so < 4; so++) {
                int s = w * 4 + so;
                float acc = 0.f;
#pragma unroll
                for (int eblk = 0; eblk < 16; eblk++) {
                    const float* cwp = g_ctxWT +
                        ((size_t)(bpair * 16 + eblk) * 128 + brow + s) * 64;
                    acc += qs[eblk * 64 + lane] * cwp[lane];
                    acc += qs[eblk * 64 + 32 + lane] * cwp[32 + lane];
                }
#pragma unroll
                for (int off = 16; off; off >>= 1)
                    acc += __shfl_down_sync(0xffffffffu, acc, off);
                if (lane == 0) sc[s] = acc;
            }
            __syncthreads();
            if (tid < 32) {
                float v0 = sc[tid], v1 = sc[tid + 32];
                float m = fmaxf(v0, v1);
#pragma unroll
                for (int off = 16; off; off >>= 1)
                    m = fmaxf(m, __shfl_xor_sync(0xffffffffu, m, off));
                float e0 = expf(v0 - m), e1 = expf(v1 - m);
                float s = e0 + e1;
#pragma unroll
                for (int off = 16; off; off >>= 1)
                    s += __shfl_xor_sync(0xffffffffu, s, off);
                float inv = 1.f / s;
                float a0 = e0 * inv, a1 = e1 * inv;
                g_align[b * 64 + tid] = a0;
                g_align[b * 64 + tid + 32] = a1;
                float* at = attns + (size_t)t * 4096 + b * 64;
                __stcs(at + tid, a0);
                __stcs(at + tid + 32, a1);
            }
        } else {
            const int idx = bi - 64;                  // 0..63
            const int mt = idx >> 3, ks = idx & 7;    // 8 mtiles x 8 ksplits, 1 chunk
            gemm_tile(g_Wout_h, g_Wout_l, g_Zoh, g_Zol, 2048,
                      g_part + (size_t)(16 + ks) * 65536, 64, 1,
                      2048, mt * 128, 1024 + ks * 128, 1, dsm);
        }
        gsync(tgt, bi);
        // ---- P6: combine: y = sum_s align*ctxOut + sum_ks part; tanh; outputs+feed ----
        {
            float* salign = (float*)dsm;   // 64*64
            for (int i = tid; i < 4096; i += 512) salign[i] = g_align[i];
            __syncthreads();
            int e = bi * 512 + tid;
            int n = e >> 6, b = e & 63;
            float acc = 0.f;
#pragma unroll
            for (int ks = 0; ks < 8; ks++)
                acc += __ldcs(g_part + (size_t)(16 + ks) * 65536 + e);
            const float4* co = (const float4*)(g_ctxOut + (size_t)e * 64);
            const float* al = salign + b * 64;
#pragma unroll
            for (int sq = 0; sq < 16; sq++) {
                float4 v = co[sq];
                acc += al[sq * 4 + 0] * v.x + al[sq * 4 + 1] * v.y
                     + al[sq * 4 + 2] * v.z + al[sq * 4 + 3] * v.w;
            }
            float h = tanhf(acc);
            __stcs(outs + (size_t)t * 65536 + b * 1024 + n, h);
            bf16 hh, hl;
            hilo(h, hh, hl);
            g_Z0h[b * 2048 + n] = hh;
            g_Z0l[b * 2048 + n] = hl;
        }
        gsync(tgt, bi);
    }
}

// ---------------- embW precompute: [t][n][b] = emb_t @ W0e^T ----------------
__global__ void __launch_bounds__(512) gemm_pre(float* __restrict__ out)
{
    extern __shared__ __align__(16) char dsm[];
    gemm_tile(g_W0e_h, g_W0e_l,
              g_embh + (size_t)blockIdx.y * 65536, g_embl + (size_t)blockIdx.y * 65536, 1024,
              out + (size_t)blockIdx.y * 262144, 64, 1,
              1024, blockIdx.x * 128, 0, 8, dsm);
}

// ---------------- ctxW precompute: scores matrix ----------------
__global__ void __launch_bounds__(512) ctxw_pre(float* __restrict__ out)
{
    extern __shared__ __align__(16) char dsm[];
    const int bpair = blockIdx.x;   // 32
    const int eblk  = blockIdx.y;   // 16
    gemm_tile(g_ctxRh + (size_t)bpair * 131072, g_ctxRl + (size_t)bpair * 131072,
              g_WinT_h + (size_t)eblk * 65536, g_WinT_l + (size_t)eblk * 65536, 1024,
              out + ((size_t)bpair * 16 + eblk) * 8192, 64, 1,
              1024, 0, 0, 8, dsm);
}

// ---------------- ctxOut precompute: [(n*64+b)][s] = Wout_cvec . ctx[s,b] ----------------
__global__ void __launch_bounds__(512) ctxout_pre(float* __restrict__ out)
{
    extern __shared__ __align__(16) char dsm[];
    const int mt = blockIdx.x;   // 8
    const int s  = blockIdx.y;   // 64
    gemm_tile(g_Wout_h, g_Wout_l,
              g_ctxPh + (size_t)s * 65536, g_ctxPl + (size_t)s * 65536, 1024,
              out + s, 4096, 64,
              2048, mt * 128, 0, 8, dsm);
}

// ---------------- init state ----------------
__global__ void init_state(const float* __restrict__ input_feed,
                           const float* __restrict__ h0, const float* __restrict__ c0)
{
    int e = blockIdx.x * blockDim.x + threadIdx.x;  // 65536
    int b = e >> 10, d = e & 1023;
    bf16 hh, hl;
    hilo(input_feed[e], hh, hl);
    g_Z0h[b * 2048 + d] = hh; g_Z0l[b * 2048 + d] = hl;
    hilo(h0[e], hh, hl);
    g_Z0h[b * 2048 + 1024 + d] = hh; g_Z0l[b * 2048 + 1024 + d] = hl;
    hilo(h0[65536 + e], hh, hl);
    g_Z1h[b * 2048 + 1024 + d] = hh; g_Z1l[b * 2048 + 1024 + d] = hl;
    g_cT0[d * 64 + b] = c0[e];
    g_cT1[d * 64 + b] = c0[65536 + e];
}

// ---------------- weight prep ----------------
__global__ void prep_w(const float* __restrict__ W_ih0, const float* __restrict__ W_hh0,
                       const float* __restrict__ W_ih1, const float* __restrict__ W_hh1,
                       const float* __restrict__ W_in,  const float* __restrict__ W_out,
                       const float* __restrict__ emb,   const float* __restrict__ ctx,
                       const float* __restrict__ b_ih0, const float* __restrict__ b_hh0,
                       const float* __restrict__ b_ih1, const float* __restrict__ b_hh1)
{
    size_t stride = (size_t)gridDim.x * blockDim.x;
    for (size_t i = (size_t)blockIdx.x * blockDim.x + threadIdx.x;
         i < 4096ull * 2048ull; i += stride) {
        size_t n = i >> 11, k = i & 2047;
        float v0 = (k < 1024) ? W_ih0[n * 2048 + 1024 + k] : W_hh0[n * 1024 + (k - 1024)];
        hilo(v0, g_Wc0_h[i], g_Wc0_l[i]);
        float v1 = (k < 1024) ? W_ih1[n * 1024 + k] : W_hh1[n * 1024 + (k - 1024)];
        hilo(v1, g_Wc1_h[i], g_Wc1_l[i]);
        if (n < 1024) hilo(W_out[i], g_Wout_h[i], g_Wout_l[i]);
        if (i < 4096ull * 1024ull) {
            size_t nn = i >> 10, kk = i & 1023;
            hilo(W_ih0[nn * 2048 + kk], g_W0e_h[i], g_W0e_l[i]);
            hilo(emb[i], g_embh[i], g_embl[i]);
            hilo(ctx[i], g_ctxPh[i], g_ctxPl[i]);
            size_t b = (i >> 10) & 63, s = i >> 16, d = i & 1023;
            size_t ri = ((b >> 1) * 128 + (b & 1) * 64 + s) * 1024 + d;
            hilo(ctx[i], g_ctxRh[ri], g_ctxRl[ri]);
        }
        if (i < 1024ull * 1024ull) {
            size_t ti = (i & 1023) * 1024 + (i >> 10);
            hilo(W_in[i], g_WinT_h[ti], g_WinT_l[ti]);
        }
        if (i < 4096) {
            g_bias0[i] = b_ih0[i] + b_hh0[i];
            g_bias1[i] = b_ih1[i] + b_hh1[i];
        }
    }
}

// ---------------- host orchestration ----------------
extern "C" void kernel_launch(void* const* d_in, const int* in_sizes, int n_in,
                              void* d_out, int out_size)
{
    (void)in_sizes; (void)n_in; (void)out_size;
    const float* emb        = (const float*)d_in[0];
    const float* context    = (const float*)d_in[1];
    const float* input_feed = (const float*)d_in[2];
    const float* h0         = (const float*)d_in[3];
    const float* c0         = (const float*)d_in[4];
    const float* W_ih0      = (const float*)d_in[5];
    const float* W_hh0      = (const float*)d_in[6];
    const float* b_ih0      = (const float*)d_in[7];
    const float* b_hh0      = (const float*)d_in[8];
    const float* W_ih1      = (const float*)d_in[9];
    const float* W_hh1      = (const float*)d_in[10];
    const float* b_ih1      = (const float*)d_in[11];
    const float* b_hh1      = (const float*)d_in[12];
    const float* W_in       = (const float*)d_in[13];
    const float* W_out      = (const float*)d_in[14];

    float* outs  = (float*)d_out;
    float* attns = outs + 64 * 64 * 1024;

    static bool attr_set = false;
    if (!attr_set) {
        cudaFuncSetAttribute(persistent_k, cudaFuncAttributeMaxDynamicSharedMemorySize, GEMM_SMEM);
        cudaFuncSetAttribute(gemm_pre, cudaFuncAttributeMaxDynamicSharedMemorySize, GEMM_SMEM);
        cudaFuncSetAttribute(ctxw_pre, cudaFuncAttributeMaxDynamicSharedMemorySize, GEMM_SMEM);
        cudaFuncSetAttribute(ctxout_pre, cudaFuncAttributeMaxDynamicSharedMemorySize, GEMM_SMEM);
        attr_set = true;
    }

    float *pEmbW, *pCtxWT, *pCtxOut;
    cudaGetSymbolAddress((void**)&pEmbW, g_embW);
    cudaGetSymbolAddress((void**)&pCtxWT, g_ctxWT);
    cudaGetSymbolAddress((void**)&pCtxOut, g_ctxOut);

    prep_w<<<4096, 256>>>(W_ih0, W_hh0, W_ih1, W_hh1, W_in, W_out, emb, context,
                          b_ih0, b_hh0, b_ih1, b_hh1);
    init_state<<<256, 256>>>(input_feed, h0, c0);
    ctxw_pre<<<dim3(32, 16), 512, GEMM_SMEM>>>(pCtxWT);
    ctxout_pre<<<dim3(8, 64), 512, GEMM_SMEM>>>(pCtxOut);
    gemm_pre<<<dim3(32, 64), 512, GEMM_SMEM>>>(pEmbW);
    persistent_k<<<NCTA, 512, GEMM_SMEM>>>(outs, attns);
}

// round 13
// speedup vs baseline: 1.1771x; 1.1471x over previous
#include <cuda_runtime.h>
#include <cuda_bf16.h>
#include <cuda_fp16.h>
#include <cstdint>
#include <math.h>

typedef __nv_bfloat16 bf16;

// Shapes: T=64, B=64, S=64, E=1024, D=1024, G=4096
// Persistent kernel: 128 CTAs x 512 threads, one CTA per SM, 6 fast barriers/step.
// Hot-path GEMMs: 2-term fp16 (W = hi + lo*2^-11, lo stored prescaled by 2^11 and
// accumulated separately; Z single fp16), mma.sync m16n8k16 f16->f32.
// Precompute GEMMs (ctxW scores, ctxOut) stay 3-term hi/lo bf16 for full precision.
// attn_h = tanh( sum_s align[s]*ctxOut[s,b,:] + Wout_h1 . h1 ).

#define NCTA 128

// ---------------- static device scratch ----------------
// fp16 2-term loop weights
__device__ __align__(16) __half g_W0eH[4096*1024], g_W0eL[4096*1024];  // W_ih0[:, :1024]
__device__ __align__(16) __half g_Wc0H[4096*2048], g_Wc0L[4096*2048];  // [W_ih0[:,1024:] | W_hh0]
__device__ __align__(16) __half g_Wc1H[4096*2048], g_Wc1L[4096*2048];  // [W_ih1 | W_hh1]
__device__ __align__(16) __half g_WoH1[1024*1024], g_WoL1[1024*1024];  // W_out[:, 1024:]
__device__ __align__(16) __half g_embH[4096*1024];                     // emb rows (t*64+b)
// bf16 3-term precompute operands
__device__ __align__(16) bf16 g_WinT_h[1024*1024], g_WinT_l[1024*1024];// W_in^T: [e][d]
__device__ __align__(16) bf16 g_Wout_h[1024*2048], g_Wout_l[1024*2048];
__device__ __align__(16) bf16 g_ctxRh[4096*1024], g_ctxRl[4096*1024];  // ctx repacked per bpair
__device__ __align__(16) bf16 g_ctxPh[4096*1024], g_ctxPl[4096*1024];  // ctx plain [(s*64+b)][d]
// fp32 precomputes + state
__device__ __align__(16) float g_ctxWT[64*64*1024];  // [(bpair*16+eblk)][srow(128)][elocal(64)]
__device__ __align__(16) float g_ctxOut[1024*64*64]; // [(n*64+b)][s]
__device__ __align__(16) float g_embW[64*4096*64];   // [t][n][b]
__device__ __align__(16) float g_part[24*1024*64];   // split-K partials
__device__ __align__(16) __half g_Z0f[64*2048];      // [feed | h0_prev] fp16
__device__ __align__(16) __half g_Z1f[64*2048];      // [h0_new | h1] fp16
__device__ __align__(16) float g_h1f[64*1024];       // fp32 h1 [b][d]
__device__ __align__(16) float g_align[64*64];       // align [b][s]
__device__ __align__(16) float g_cT0[1024*64], g_cT1[1024*64];
__device__ __align__(16) float g_bias0[4096], g_bias1[4096];
__device__ volatile int g_arrive[NCTA];
__device__ volatile int g_release;

// ---------------- PTX helpers ----------------
__device__ __forceinline__ uint32_t smem_u32(const void* p) {
    uint32_t a;
    asm("{ .reg .u64 t; cvta.to.shared.u64 t, %1; cvt.u32.u64 %0, t; }" : "=r"(a) : "l"(p));
    return a;
}
__device__ __forceinline__ void ldm4(uint32_t* r, uint32_t a) {
    asm volatile("ldmatrix.sync.aligned.m8n8.x4.shared.b16 {%0,%1,%2,%3}, [%4];"
                 : "=r"(r[0]), "=r"(r[1]), "=r"(r[2]), "=r"(r[3]) : "r"(a));
}
__device__ __forceinline__ void mma_bf16(float* c, const uint32_t* a, uint32_t b0, uint32_t b1) {
    asm volatile("mma.sync.aligned.m16n8k16.row.col.f32.bf16.bf16.f32 "
                 "{%0,%1,%2,%3}, {%4,%5,%6,%7}, {%8,%9}, {%0,%1,%2,%3};"
                 : "+f"(c[0]), "+f"(c[1]), "+f"(c[2]), "+f"(c[3])
                 : "r"(a[0]), "r"(a[1]), "r"(a[2]), "r"(a[3]), "r"(b0), "r"(b1));
}
__device__ __forceinline__ void mma_f16(float* c, const uint32_t* a, uint32_t b0, uint32_t b1) {
    asm volatile("mma.sync.aligned.m16n8k16.row.col.f32.f16.f16.f32 "
                 "{%0,%1,%2,%3}, {%4,%5,%6,%7}, {%8,%9}, {%0,%1,%2,%3};"
                 : "+f"(c[0]), "+f"(c[1]), "+f"(c[2]), "+f"(c[3])
                 : "r"(a[0]), "r"(a[1]), "r"(a[2]), "r"(a[3]), "r"(b0), "r"(b1));
}
__device__ __forceinline__ void cpa16(uint32_t s, const void* g) {
    asm volatile("cp.async.cg.shared.global [%0], [%1], 16;" :: "r"(s), "l"(g));
}
#define CP_COMMIT() asm volatile("cp.async.commit_group;" ::: "memory")

__device__ __forceinline__ void hilo(float x, bf16& h, bf16& l) {
    h = __float2bfloat16(x);
    l = __float2bfloat16(x - __bfloat162float(h));
}
// fp16 split with lo prescaled by 2^11 (keeps lo in normal fp16 range)
__device__ __forceinline__ void hiloH(float x, __half& h, __half& l) {
    h = __float2half_rn(x);
    l = __float2half_rn((x - __half2float(h)) * 2048.0f);
}

// fast global barrier: per-CTA arrive flags + CTA0 scan + release word
__device__ __forceinline__ void gsync(int& tgt, int bi) {
    __syncthreads();
    tgt++;
    if (threadIdx.x == 0) { __threadfence(); g_arrive[bi] = tgt; }
    if (bi == 0) {
        if (threadIdx.x < NCTA) {
            while (g_arrive[threadIdx.x] - tgt < 0) {}
        }
        __syncthreads();
        if (threadIdx.x == 0) { __threadfence(); g_release = tgt; }
    } else {
        if (threadIdx.x == 0) {
            while (g_release - tgt < 0) {}
            __threadfence();
        }
    }
    __syncthreads();
}

// ---------------- shared tile constants (Kchunk=128) ----------------
static constexpr int PITCH = 136;                   // 16-bit elems; 272B rows
static constexpr int WBYTES = 128 * PITCH * 2;      // 34816
static constexpr int ZBYTES = 64 * PITCH * 2;       // 17408
static constexpr int BUF3 = 2 * WBYTES + 2 * ZBYTES;   // 104448 (bf16 3-term)
static constexpr int BUF2 = 2 * WBYTES + ZBYTES;       // 87040  (fp16 2-term)
static constexpr int GEMM_SMEM = 2 * BUF3;             // 208896

// ---------------- bf16 3-term GEMM tile (precompute kernels) ----------------
__device__ __forceinline__ void gemm3t(
    const bf16* __restrict__ Wh, const bf16* __restrict__ Wl,
    const bf16* __restrict__ Zh, const bf16* __restrict__ Zl, int ldz,
    float* __restrict__ out, size_t strideM, int strideB,
    int K, int n0, int k0, int chunks, char* dsm)
{
    const int tid  = threadIdx.x;
    const int lane = tid & 31, wid = tid >> 5;
    const int wm = wid >> 2, wn = wid & 3;
    const uint32_t sb = smem_u32(dsm);

    float acc[2][2][4];
#pragma unroll
    for (int mi = 0; mi < 2; mi++)
#pragma unroll
        for (int nj = 0; nj < 2; nj++)
#pragma unroll
            for (int q = 0; q < 4; q++) acc[mi][nj][q] = 0.f;

    auto stage = [&](int c) {
        const uint32_t S = sb + (c & 1) * BUF3;
        const int kb = k0 + c * 128;
#pragma unroll
        for (int i = 0; i < 4; i++) {
            int idx = i * 512 + tid;
            int row = idx >> 4, cg = idx & 15;
            size_t g = (size_t)(n0 + row) * K + kb + cg * 8;
            uint32_t d = S + (row * PITCH + cg * 8) * 2;
            cpa16(d, Wh + g);
            cpa16(d + WBYTES, Wl + g);
        }
#pragma unroll
        for (int i = 0; i < 2; i++) {
            int idx = i * 512 + tid;
            int row = idx >> 4, cg = idx & 15;
            size_t g = (size_t)row * ldz + kb + cg * 8;
            uint32_t d = S + 2 * WBYTES + (row * PITCH + cg * 8) * 2;
            cpa16(d, Zh + g);
            cpa16(d + ZBYTES, Zl + g);
        }
        CP_COMMIT();
    };

    stage(0);
    for (int c = 0; c < chunks; c++) {
        if (c + 1 < chunks) {
            stage(c + 1);
            asm volatile("cp.async.wait_group 1;" ::: "memory");
        } else {
            asm volatile("cp.async.wait_group 0;" ::: "memory");
        }
        __syncthreads();

        const uint32_t S = sb + (c & 1) * BUF3;
        const uint32_t aw = S + ((wm * 32 + (lane & 15)) * PITCH + (lane >> 4) * 8) * 2;
        const uint32_t bz = S + 2 * WBYTES + ((wn * 16 + (lane & 15)) * PITCH + (lane >> 4) * 8) * 2;

#pragma unroll
        for (int ks = 0; ks < 8; ks++) {
            const uint32_t koff = ks * 32;
            uint32_t ah[2][4], al[2][4], bh[4], bl[4];
#pragma unroll
            for (int mi = 0; mi < 2; mi++) {
                uint32_t a = aw + mi * 16 * PITCH * 2 + koff;
                ldm4(ah[mi], a);
                ldm4(al[mi], a + WBYTES);
            }
            ldm4(bh, bz + koff);
            ldm4(bl, bz + koff + ZBYTES);
#pragma unroll
            for (int mi = 0; mi < 2; mi++)
#pragma unroll
                for (int nj = 0; nj < 2; nj++) {
                    mma_bf16(acc[mi][nj], ah[mi], bh[nj], bh[2 + nj]);
                    mma_bf16(acc[mi][nj], ah[mi], bl[nj], bl[2 + nj]);
                    mma_bf16(acc[mi][nj], al[mi], bh[nj], bh[2 + nj]);
                }
        }
        __syncthreads();
    }

#pragma unroll
    for (int mi = 0; mi < 2; mi++)
#pragma unroll
        for (int nj = 0; nj < 2; nj++) {
            int m = n0 + wm * 32 + mi * 16 + (lane >> 2);
            int b = wn * 16 + nj * 8 + (lane & 3) * 2;
            if (strideB == 1) {
                __stcs((float2*)(out + (size_t)m * strideM + b),
                       make_float2(acc[mi][nj][0], acc[mi][nj][1]));
                __stcs((float2*)(out + (size_t)(m + 8) * strideM + b),
                       make_float2(acc[mi][nj][2], acc[mi][nj][3]));
            } else {
                out[(size_t)m * strideM + (size_t)b * strideB]             = acc[mi][nj][0];
                out[(size_t)m * strideM + (size_t)(b + 1) * strideB]       = acc[mi][nj][1];
                out[(size_t)(m + 8) * strideM + (size_t)b * strideB]       = acc[mi][nj][2];
                out[(size_t)(m + 8) * strideM + (size_t)(b + 1) * strideB] = acc[mi][nj][3];
            }
        }
}

// ---------------- fp16 2-term GEMM tile (hot path) ----------------
// out[m*64+b] = sum_k (Wh[m][k] + Wl[m][k]*2^-11) * Z[b][k]
__device__ __forceinline__ void gemm2(
    const __half* __restrict__ Wh, const __half* __restrict__ Wl,
    const __half* __restrict__ Z, int ldz,
    float* __restrict__ out,
    int K, int n0, int k0, int chunks, char* dsm)
{
    const int tid  = threadIdx.x;
    const int lane = tid & 31, wid = tid >> 5;
    const int wm = wid >> 2, wn = wid & 3;
    const uint32_t sb = smem_u32(dsm);

    float accH[2][2][4], accL[2][2][4];
#pragma unroll
    for (int mi = 0; mi < 2; mi++)
#pragma unroll
        for (int nj = 0; nj < 2; nj++)
#pragma unroll
            for (int q = 0; q < 4; q++) { accH[mi][nj][q] = 0.f; accL[mi][nj][q] = 0.f; }

    auto stage = [&](int c) {
        const uint32_t S = sb + (c & 1) * BUF2;
        const int kb = k0 + c * 128;
#pragma unroll
        for (int i = 0; i < 4; i++) {
            int idx = i * 512 + tid;
            int row = idx >> 4, cg = idx & 15;
            size_t g = (size_t)(n0 + row) * K + kb + cg * 8;
            uint32_t d = S + (row * PITCH + cg * 8) * 2;
            cpa16(d, Wh + g);
            cpa16(d + WBYTES, Wl + g);
        }
#pragma unroll
        for (int i = 0; i < 2; i++) {
            int idx = i * 512 + tid;
            int row = idx >> 4, cg = idx & 15;
            size_t g = (size_t)row * ldz + kb + cg * 8;
            cpa16(S + 2 * WBYTES + (row * PITCH + cg * 8) * 2, Z + g);
        }
        CP_COMMIT();
    };

    stage(0);
    for (int c = 0; c < chunks; c++) {
        if (c + 1 < chunks) {
            stage(c + 1);
            asm volatile("cp.async.wait_group 1;" ::: "memory");
        } else {
            asm volatile("cp.async.wait_group 0;" ::: "memory");
        }
        __syncthreads();

        const uint32_t S = sb + (c & 1) * BUF2;
        const uint32_t aw = S + ((wm * 32 + (lane & 15)) * PITCH + (lane >> 4) * 8) * 2;
        const uint32_t bz = S + 2 * WBYTES + ((wn * 16 + (lane & 15)) * PITCH + (lane >> 4) * 8) * 2;

#pragma unroll
        for (int ks = 0; ks < 8; ks++) {
            const uint32_t koff = ks * 32;
            uint32_t ah[2][4], al[2][4], bh[4];
#pragma unroll
            for (int mi = 0; mi < 2; mi++) {
                uint32_t a = aw + mi * 16 * PITCH * 2 + koff;
                ldm4(ah[mi], a);
                ldm4(al[mi], a + WBYTES);
            }
            ldm4(bh, bz + koff);
#pragma unroll
            for (int mi = 0; mi < 2; mi++)
#pragma unroll
                for (int nj = 0; nj < 2; nj++) {
                    mma_f16(accH[mi][nj], ah[mi], bh[nj], bh[2 + nj]);
                    mma_f16(accL[mi][nj], al[mi], bh[nj], bh[2 + nj]);
                }
        }
        __syncthreads();
    }

    const float s = 1.0f / 2048.0f;
#pragma unroll
    for (int mi = 0; mi < 2; mi++)
#pragma unroll
        for (int nj = 0; nj < 2; nj++) {
            int m = n0 + wm * 32 + mi * 16 + (lane >> 2);
            int b = wn * 16 + nj * 8 + (lane & 3) * 2;
            __stcs((float2*)(out + (size_t)m * 64 + b),
                   make_float2(accH[mi][nj][0] + s * accL[mi][nj][0],
                               accH[mi][nj][1] + s * accL[mi][nj][1]));
            __stcs((float2*)(out + (size_t)(m + 8) * 64 + b),
                   make_float2(accH[mi][nj][2] + s * accL[mi][nj][2],
                               accH[mi][nj][3] + s * accL[mi][nj][3]));
        }
}

// ---------------- cell phase ----------------
__device__ __forceinline__ void cell_phase(
    int e, const float* __restrict__ part,
    const float* __restrict__ base, const float* __restrict__ bias,
    float* __restrict__ cT,
    __half* hA, int offA, __half* hB, int offB,
    float* __restrict__ h1f)
{
    int d = e >> 6, b = e & 63;
    float g[4];
#pragma unroll
    for (int j = 0; j < 4; j++) {
        float acc = bias[j * 1024 + d];
        if (base) acc += __ldcs(base + (size_t)j * 65536 + e);
#pragma unroll
        for (int ks = 0; ks < 4; ks++)
            acc += __ldcs(part + (size_t)ks * 262144 + (size_t)j * 65536 + e);
        g[j] = acc;
    }
    float ig = 1.f / (1.f + expf(-g[0]));
    float fg = 1.f / (1.f + expf(-g[1]));
    float gg = tanhf(g[2]);
    float og = 1.f / (1.f + expf(-g[3]));
    float cn = fg * cT[e] + ig * gg;
    float h  = og * tanhf(cn);
    cT[e] = cn;
    __half hv = __float2half_rn(h);
    hA[b * 2048 + offA + d] = hv;
    hB[b * 2048 + offB + d] = hv;
    if (h1f) h1f[b * 1024 + d] = h;
}

// ---------------- persistent kernel ----------------
__global__ void __launch_bounds__(512) persistent_k(
    float* __restrict__ outs, float* __restrict__ attns)
{
    extern __shared__ __align__(16) char dsm[];
    const int bi = blockIdx.x, tid = threadIdx.x;
    const int lane = tid & 31, w = tid >> 5;
    int tgt = g_release;

    for (int t = 0; t < 64; t++) {
        // ---- P1: LSTM0 GEMM: [feed|h0] K=2048; 32 mtiles x 4 ks, 4 chunks ----
        gemm2(g_Wc0H, g_Wc0L, g_Z0f, 2048,
              g_part + (size_t)(bi & 3) * 262144,
              2048, (bi >> 2) * 128, (bi & 3) * 512, 4, dsm);
        gsync(tgt, bi);
        // ---- P2: cell0 (adds precomputed embW base) ----
        cell_phase(bi * 512 + tid, g_part, g_embW + (size_t)t * 262144, g_bias0,
                   g_cT0, g_Z1f, 0, g_Z0f, 1024, nullptr);
        gsync(tgt, bi);
        // ---- P3: LSTM1 GEMM ----
        gemm2(g_Wc1H, g_Wc1L, g_Z1f, 2048,
              g_part + (size_t)(bi & 3) * 262144,
              2048, (bi >> 2) * 128, (bi & 3) * 512, 4, dsm);
        gsync(tgt, bi);
        // ---- P4: cell1 (h1 -> Z1f[:,1024:], also fp32 h1) ----
        cell_phase(bi * 512 + tid, g_part, nullptr, g_bias1,
                   g_cT1, g_Z1f, 1024, g_Z1f, 1024, g_h1f);
        gsync(tgt, bi);
        // ---- P5: CTAs 0-63 scores+softmax; CTAs 64-127 out-GEMM (h1 half, K=1024) ----
        if (bi < 64) {
            const int b = bi;
            float* qs = (float*)dsm;          // 1024 fp32 h1[b]
            float* sc = qs + 1024;            // 64 scores
            for (int d = tid; d < 1024; d += 512) qs[d] = g_h1f[b * 1024 + d];
            __syncthreads();
            const int bpair = b >> 1, brow = (b & 1) * 64;
#pragma unroll
            for (int so = 0; so < 4; so++) {
                int s = w * 4 + so;
                float acc = 0.f;
#pragma unroll
                for (int eblk = 0; eblk < 16; eblk++) {
                    const float* cwp = g_ctxWT +
                        ((size_t)(bpair * 16 + eblk) * 128 + brow + s) * 64;
                    acc += qs[eblk * 64 + lane] * cwp[lane];
                    acc += qs[eblk * 64 + 32 + lane] * cwp[32 + lane];
                }
#pragma unroll
                for (int off = 16; off; off >>= 1)
                    acc += __shfl_down_sync(0xffffffffu, acc, off);
                if (lane == 0) sc[s] = acc;
            }
            __syncthreads();
            if (tid < 32) {
                float v0 = sc[tid], v1 = sc[tid + 32];
                float m = fmaxf(v0, v1);
#pragma unroll
                for (int off = 16; off; off >>= 1)
                    m = fmaxf(m, __shfl_xor_sync(0xffffffffu, m, off));
                float e0 = expf(v0 - m), e1 = expf(v1 - m);
                float s = e0 + e1;
#pragma unroll
                for (int off = 16; off; off >>= 1)
                    s += __shfl_xor_sync(0xffffffffu, s, off);
                float inv = 1.f / s;
                float a0 = e0 * inv, a1 = e1 * inv;
                g_align[b * 64 + tid] = a0;
                g_align[b * 64 + tid + 32] = a1;
                float* at = attns + (size_t)t * 4096 + b * 64;
                __stcs(at + tid, a0);
                __stcs(at + tid + 32, a1);
            }
        } else {
            const int idx = bi - 64;                  // 0..63
            const int mt = idx >> 3, ks = idx & 7;    // 8 mtiles x 8 ksplits, 1 chunk
            gemm2(g_WoH1, g_WoL1, g_Z1f + 1024, 2048,
                  g_part + (size_t)(16 + ks) * 65536,
                  1024, mt * 128, ks * 128, 1, dsm);
        }
        gsync(tgt, bi);
        // ---- P6: combine: y = sum_s align*ctxOut + sum_ks part; tanh; outputs+feed ----
        {
            float* salign = (float*)dsm;   // 64*64
            for (int i = tid; i < 4096; i += 512) salign[i] = g_align[i];
            __syncthreads();
            int e = bi * 512 + tid;
            int n = e >> 6, b = e & 63;
            float acc = 0.f;
#pragma unroll
            for (int ks = 0; ks < 8; ks++)
                acc += __ldcs(g_part + (size_t)(16 + ks) * 65536 + e);
            const float4* co = (const float4*)(g_ctxOut + (size_t)e * 64);
            const float* al = salign + b * 64;
#pragma unroll
            for (int sq = 0; sq < 16; sq++) {
                float4 v = co[sq];
                acc += al[sq * 4 + 0] * v.x + al[sq * 4 + 1] * v.y
                     + al[sq * 4 + 2] * v.z + al[sq * 4 + 3] * v.w;
            }
            float h = tanhf(acc);
            __stcs(outs + (size_t)t * 65536 + b * 1024 + n, h);
            g_Z0f[b * 2048 + n] = __float2half_rn(h);
        }
        gsync(tgt, bi);
    }
}

// ---------------- embW precompute: [t][n][b] = emb_t @ W0e^T (fp16 2-term) ----------------
__global__ void __launch_bounds__(512) gemm_pre(float* __restrict__ out)
{
    extern __shared__ __align__(16) char dsm[];
    gemm2(g_W0eH, g_W0eL, g_embH + (size_t)blockIdx.y * 65536, 1024,
          out + (size_t)blockIdx.y * 262144,
          1024, blockIdx.x * 128, 0, 8, dsm);
}

// ---------------- ctxW precompute: scores matrix (bf16 3-term) ----------------
__global__ void __launch_bounds__(512) ctxw_pre(float* __restrict__ out)
{
    extern __shared__ __align__(16) char dsm[];
    const int bpair = blockIdx.x;   // 32
    const int eblk  = blockIdx.y;   // 16
    gemm3t(g_ctxRh + (size_t)bpair * 131072, g_ctxRl + (size_t)bpair * 131072,
           g_WinT_h + (size_t)eblk * 65536, g_WinT_l + (size_t)eblk * 65536, 1024,
           out + ((size_t)bpair * 16 + eblk) * 8192, 64, 1,
           1024, 0, 0, 8, dsm);
}

// ---------------- ctxOut precompute (bf16 3-term) ----------------
__global__ void __launch_bounds__(512) ctxout_pre(float* __restrict__ out)
{
    extern __shared__ __align__(16) char dsm[];
    const int mt = blockIdx.x;   // 8
    const int s  = blockIdx.y;   // 64
    gemm3t(g_Wout_h, g_Wout_l,
           g_ctxPh + (size_t)s * 65536, g_ctxPl + (size_t)s * 65536, 1024,
           out + s, 4096, 64,
           2048, mt * 128, 0, 8, dsm);
}

// ---------------- init state ----------------
__global__ void init_state(const float* __restrict__ input_feed,
                           const float* __restrict__ h0, const float* __restrict__ c0)
{
    int e = blockIdx.x * blockDim.x + threadIdx.x;  // 65536
    int b = e >> 10, d = e & 1023;
    g_Z0f[b * 2048 + d] = __float2half_rn(input_feed[e]);
    g_Z0f[b * 2048 + 1024 + d] = __float2half_rn(h0[e]);
    g_Z1f[b * 2048 + 1024 + d] = __float2half_rn(h0[65536 + e]);
    g_cT0[d * 64 + b] = c0[e];
    g_cT1[d * 64 + b] = c0[65536 + e];
}

// ---------------- weight prep ----------------
__global__ void prep_w(const float* __restrict__ W_ih0, const float* __restrict__ W_hh0,
                       const float* __restrict__ W_ih1, const float* __restrict__ W_hh1,
                       const float* __restrict__ W_in,  const float* __restrict__ W_out,
                       const float* __restrict__ emb,   const float* __restrict__ ctx,
                       const float* __restrict__ b_ih0, const float* __restrict__ b_hh0,
                       const float* __restrict__ b_ih1, const float* __restrict__ b_hh1)
{
    size_t stride = (size_t)gridDim.x * blockDim.x;
    for (size_t i = (size_t)blockIdx.x * blockDim.x + threadIdx.x;
         i < 4096ull * 2048ull; i += stride) {
        size_t n = i >> 11, k = i & 2047;
        float v0 = (k < 1024) ? W_ih0[n * 2048 + 1024 + k] : W_hh0[n * 1024 + (k - 1024)];
        hiloH(v0, g_Wc0H[i], g_Wc0L[i]);
        float v1 = (k < 1024) ? W_ih1[n * 1024 + k] : W_hh1[n * 1024 + (k - 1024)];
        hiloH(v1, g_Wc1H[i], g_Wc1L[i]);
        if (n < 1024) {
            hilo(W_out[i], g_Wout_h[i], g_Wout_l[i]);           // bf16 for ctxout_pre
            if (k >= 1024)
                hiloH(W_out[i], g_WoH1[n * 1024 + (k - 1024)],  // fp16 for loop
                               g_WoL1[n * 1024 + (k - 1024)]);
        }
        if (i < 4096ull * 1024ull) {
            size_t nn = i >> 10, kk = i & 1023;
            hiloH(W_ih0[nn * 2048 + kk], g_W0eH[i], g_W0eL[i]);
            g_embH[i] = __float2half_rn(emb[i]);
            hilo(ctx[i], g_ctxPh[i], g_ctxPl[i]);
            size_t b = (i >> 10) & 63, s = i >> 16, d = i & 1023;
            size_t ri = ((b >> 1) * 128 + (b & 1) * 64 + s) * 1024 + d;
            hilo(ctx[i], g_ctxRh[ri], g_ctxRl[ri]);
        }
        if (i < 1024ull * 1024ull) {
            size_t ti = (i & 1023) * 1024 + (i >> 10);
            hilo(W_in[i], g_WinT_h[ti], g_WinT_l[ti]);
        }
        if (i < 4096) {
            g_bias0[i] = b_ih0[i] + b_hh0[i];
            g_bias1[i] = b_ih1[i] + b_hh1[i];
        }
    }
}

// ---------------- host orchestration ----------------
extern "C" void kernel_launch(void* const* d_in, const int* in_sizes, int n_in,
                              void* d_out, int out_size)
{
    (void)in_sizes; (void)n_in; (void)out_size;
    const float* emb        = (const float*)d_in[0];
    const float* context    = (const float*)d_in[1];
    const float* input_feed = (const float*)d_in[2];
    const float* h0         = (const float*)d_in[3];
    const float* c0         = (const float*)d_in[4];
    const float* W_ih0      = (const float*)d_in[5];
    const float* W_hh0      = (const float*)d_in[6];
    const float* b_ih0      = (const float*)d_in[7];
    const float* b_hh0      = (const float*)d_in[8];
    const float* W_ih1      = (const float*)d_in[9];
    const float* W_hh1      = (const float*)d_in[10];
    const float* b_ih1      = (const float*)d_in[11];
    const float* b_hh1      = (const float*)d_in[12];
    const float* W_in       = (const float*)d_in[13];
    const float* W_out      = (const float*)d_in[14];

    float* outs  = (float*)d_out;
    float* attns = outs + 64 * 64 * 1024;

    static bool attr_set = false;
    if (!attr_set) {
        cudaFuncSetAttribute(persistent_k, cudaFuncAttributeMaxDynamicSharedMemorySize, GEMM_SMEM);
        cudaFuncSetAttribute(gemm_pre, cudaFuncAttributeMaxDynamicSharedMemorySize, GEMM_SMEM);
        cudaFuncSetAttribute(ctxw_pre, cudaFuncAttributeMaxDynamicSharedMemorySize, GEMM_SMEM);
        cudaFuncSetAttribute(ctxout_pre, cudaFuncAttributeMaxDynamicSharedMemorySize, GEMM_SMEM);
        attr_set = true;
    }

    float *pEmbW, *pCtxWT, *pCtxOut;
    cudaGetSymbolAddress((void**)&pEmbW, g_embW);
    cudaGetSymbolAddress((void**)&pCtxWT, g_ctxWT);
    cudaGetSymbolAddress((void**)&pCtxOut, g_ctxOut);

    prep_w<<<4096, 256>>>(W_ih0, W_hh0, W_ih1, W_hh1, W_in, W_out, emb, context,
                          b_ih0, b_hh0, b_ih1, b_hh1);
    init_state<<<256, 256>>>(input_feed, h0, c0);
    ctxw_pre<<<dim3(32, 16), 512, GEMM_SMEM>>>(pCtxWT);
    ctxout_pre<<<dim3(8, 64), 512, GEMM_SMEM>>>(pCtxOut);
    gemm_pre<<<dim3(32, 64), 512, GEMM_SMEM>>>(pEmbW);
    persistent_k<<<NCTA, 512, GEMM_SMEM>>>(outs, attns);
}

// round 14
// speedup vs baseline: 1.5343x; 1.3034x over previous
#include <cuda_runtime.h>
#include <cuda_bf16.h>
#include <cuda_fp16.h>
#include <cstdint>
#include <math.h>

typedef __nv_bfloat16 bf16;

// Shapes: T=64, B=64, S=64, E=1024, D=1024, G=4096
// Persistent kernel: 128 CTAs x 512 threads, one CTA per SM, 6 fast barriers/step.
// Hot-path GEMMs: SINGLE-term fp16 (W fp16, Z fp16), mma.sync m16n8k16 f16->f32.
//   (R13 showed product error is activation-dominated at 2^-11; the lo-weight term
//    was waste. Error budget: ~sqrt(2)*2.15e-4 ~ 3-4e-4 << 1e-3.)
// Precompute GEMMs (ctxW scores, ctxOut) stay 3-term hi/lo bf16 for full precision.
// attn_h = tanh( sum_s align[s]*ctxOut[s,b,:] + Wout_h1 . h1 ).

#define NCTA 128

// ---------------- static device scratch ----------------
// fp16 single-term loop weights
__device__ __align__(16) __half g_W0eH[4096*1024];                     // W_ih0[:, :1024]
__device__ __align__(16) __half g_Wc0H[4096*2048];                     // [W_ih0[:,1024:] | W_hh0]
__device__ __align__(16) __half g_Wc1H[4096*2048];                     // [W_ih1 | W_hh1]
__device__ __align__(16) __half g_WoH1[1024*1024];                     // W_out[:, 1024:]
__device__ __align__(16) __half g_embH[4096*1024];                     // emb rows (t*64+b)
// bf16 3-term precompute operands
__device__ __align__(16) bf16 g_WinT_h[1024*1024], g_WinT_l[1024*1024];// W_in^T: [e][d]
__device__ __align__(16) bf16 g_Wout_h[1024*2048], g_Wout_l[1024*2048];
__device__ __align__(16) bf16 g_ctxRh[4096*1024], g_ctxRl[4096*1024];  // ctx repacked per bpair
__device__ __align__(16) bf16 g_ctxPh[4096*1024], g_ctxPl[4096*1024];  // ctx plain [(s*64+b)][d]
// fp32 precomputes + state
__device__ __align__(16) float g_ctxWT[64*64*1024];  // [(bpair*16+eblk)][srow(128)][elocal(64)]
__device__ __align__(16) float g_ctxOut[1024*64*64]; // [(n*64+b)][s]
__device__ __align__(16) float g_embW[64*4096*64];   // [t][n][b]
__device__ __align__(16) float g_part[24*1024*64];   // split-K partials
__device__ __align__(16) __half g_Z0f[64*2048];      // [feed | h0_prev] fp16
__device__ __align__(16) __half g_Z1f[64*2048];      // [h0_new | h1] fp16
__device__ __align__(16) float g_h1f[64*1024];       // fp32 h1 [b][d]
__device__ __align__(16) float g_align[64*64];       // align [b][s]
__device__ __align__(16) float g_cT0[1024*64], g_cT1[1024*64];
__device__ __align__(16) float g_bias0[4096], g_bias1[4096];
__device__ volatile int g_arrive[NCTA];
__device__ volatile int g_release;

// ---------------- PTX helpers ----------------
__device__ __forceinline__ uint32_t smem_u32(const void* p) {
    uint32_t a;
    asm("{ .reg .u64 t; cvta.to.shared.u64 t, %1; cvt.u32.u64 %0, t; }" : "=r"(a) : "l"(p));
    return a;
}
__device__ __forceinline__ void ldm4(uint32_t* r, uint32_t a) {
    asm volatile("ldmatrix.sync.aligned.m8n8.x4.shared.b16 {%0,%1,%2,%3}, [%4];"
                 : "=r"(r[0]), "=r"(r[1]), "=r"(r[2]), "=r"(r[3]) : "r"(a));
}
__device__ __forceinline__ void mma_bf16(float* c, const uint32_t* a, uint32_t b0, uint32_t b1) {
    asm volatile("mma.sync.aligned.m16n8k16.row.col.f32.bf16.bf16.f32 "
                 "{%0,%1,%2,%3}, {%4,%5,%6,%7}, {%8,%9}, {%0,%1,%2,%3};"
                 : "+f"(c[0]), "+f"(c[1]), "+f"(c[2]), "+f"(c[3])
                 : "r"(a[0]), "r"(a[1]), "r"(a[2]), "r"(a[3]), "r"(b0), "r"(b1));
}
__device__ __forceinline__ void mma_f16(float* c, const uint32_t* a, uint32_t b0, uint32_t b1) {
    asm volatile("mma.sync.aligned.m16n8k16.row.col.f32.f16.f16.f32 "
                 "{%0,%1,%2,%3}, {%4,%5,%6,%7}, {%8,%9}, {%0,%1,%2,%3};"
                 : "+f"(c[0]), "+f"(c[1]), "+f"(c[2]), "+f"(c[3])
                 : "r"(a[0]), "r"(a[1]), "r"(a[2]), "r"(a[3]), "r"(b0), "r"(b1));
}
__device__ __forceinline__ void cpa16(uint32_t s, const void* g) {
    asm volatile("cp.async.cg.shared.global [%0], [%1], 16;" :: "r"(s), "l"(g));
}
#define CP_COMMIT() asm volatile("cp.async.commit_group;" ::: "memory")

__device__ __forceinline__ void hilo(float x, bf16& h, bf16& l) {
    h = __float2bfloat16(x);
    l = __float2bfloat16(x - __bfloat162float(h));
}

// fast global barrier: per-CTA arrive flags + CTA0 scan + release word
__device__ __forceinline__ void gsync(int& tgt, int bi) {
    __syncthreads();
    tgt++;
    if (threadIdx.x == 0) { __threadfence(); g_arrive[bi] = tgt; }
    if (bi == 0) {
        if (threadIdx.x < NCTA) {
            while (g_arrive[threadIdx.x] - tgt < 0) {}
        }
        __syncthreads();
        if (threadIdx.x == 0) { __threadfence(); g_release = tgt; }
    } else {
        if (threadIdx.x == 0) {
            while (g_release - tgt < 0) {}
            __threadfence();
        }
    }
    __syncthreads();
}

// ---------------- shared tile constants (Kchunk=128) ----------------
static constexpr int PITCH = 136;                   // 16-bit elems; 272B rows
static constexpr int WBYTES = 128 * PITCH * 2;      // 34816
static constexpr int ZBYTES = 64 * PITCH * 2;       // 17408
static constexpr int BUF3 = 2 * WBYTES + 2 * ZBYTES;   // 104448 (bf16 3-term)
static constexpr int BUF1 = WBYTES + ZBYTES;           // 52224  (fp16 1-term)
static constexpr int GEMM_SMEM = 2 * BUF3;             // 208896

// ---------------- bf16 3-term GEMM tile (precompute kernels) ----------------
__device__ __forceinline__ void gemm3t(
    const bf16* __restrict__ Wh, const bf16* __restrict__ Wl,
    const bf16* __restrict__ Zh, const bf16* __restrict__ Zl, int ldz,
    float* __restrict__ out, size_t strideM, int strideB,
    int K, int n0, int k0, int chunks, char* dsm)
{
    const int tid  = threadIdx.x;
    const int lane = tid & 31, wid = tid >> 5;
    const int wm = wid >> 2, wn = wid & 3;
    const uint32_t sb = smem_u32(dsm);

    float acc[2][2][4];
#pragma unroll
    for (int mi = 0; mi < 2; mi++)
#pragma unroll
        for (int nj = 0; nj < 2; nj++)
#pragma unroll
            for (int q = 0; q < 4; q++) acc[mi][nj][q] = 0.f;

    auto stage = [&](int c) {
        const uint32_t S = sb + (c & 1) * BUF3;
        const int kb = k0 + c * 128;
#pragma unroll
        for (int i = 0; i < 4; i++) {
            int idx = i * 512 + tid;
            int row = idx >> 4, cg = idx & 15;
            size_t g = (size_t)(n0 + row) * K + kb + cg * 8;
            uint32_t d = S + (row * PITCH + cg * 8) * 2;
            cpa16(d, Wh + g);
            cpa16(d + WBYTES, Wl + g);
        }
#pragma unroll
        for (int i = 0; i < 2; i++) {
            int idx = i * 512 + tid;
            int row = idx >> 4, cg = idx & 15;
            size_t g = (size_t)row * ldz + kb + cg * 8;
            uint32_t d = S + 2 * WBYTES + (row * PITCH + cg * 8) * 2;
            cpa16(d, Zh + g);
            cpa16(d + ZBYTES, Zl + g);
        }
        CP_COMMIT();
    };

    stage(0);
    for (int c = 0; c < chunks; c++) {
        if (c + 1 < chunks) {
            stage(c + 1);
            asm volatile("cp.async.wait_group 1;" ::: "memory");
        } else {
            asm volatile("cp.async.wait_group 0;" ::: "memory");
        }
        __syncthreads();

        const uint32_t S = sb + (c & 1) * BUF3;
        const uint32_t aw = S + ((wm * 32 + (lane & 15)) * PITCH + (lane >> 4) * 8) * 2;
        const uint32_t bz = S + 2 * WBYTES + ((wn * 16 + (lane & 15)) * PITCH + (lane >> 4) * 8) * 2;

#pragma unroll
        for (int ks = 0; ks < 8; ks++) {
            const uint32_t koff = ks * 32;
            uint32_t ah[2][4], al[2][4], bh[4], bl[4];
#pragma unroll
            for (int mi = 0; mi < 2; mi++) {
                uint32_t a = aw + mi * 16 * PITCH * 2 + koff;
                ldm4(ah[mi], a);
                ldm4(al[mi], a + WBYTES);
            }
            ldm4(bh, bz + koff);
            ldm4(bl, bz + koff + ZBYTES);
#pragma unroll
            for (int mi = 0; mi < 2; mi++)
#pragma unroll
                for (int nj = 0; nj < 2; nj++) {
                    mma_bf16(acc[mi][nj], ah[mi], bh[nj], bh[2 + nj]);
                    mma_bf16(acc[mi][nj], ah[mi], bl[nj], bl[2 + nj]);
                    mma_bf16(acc[mi][nj], al[mi], bh[nj], bh[2 + nj]);
                }
        }
        __syncthreads();
    }

#pragma unroll
    for (int mi = 0; mi < 2; mi++)
#pragma unroll
        for (int nj = 0; nj < 2; nj++) {
            int m = n0 + wm * 32 + mi * 16 + (lane >> 2);
            int b = wn * 16 + nj * 8 + (lane & 3) * 2;
            if (strideB == 1) {
                __stcs((float2*)(out + (size_t)m * strideM + b),
                       make_float2(acc[mi][nj][0], acc[mi][nj][1]));
                __stcs((float2*)(out + (size_t)(m + 8) * strideM + b),
                       make_float2(acc[mi][nj][2], acc[mi][nj][3]));
            } else {
                out[(size_t)m * strideM + (size_t)b * strideB]             = acc[mi][nj][0];
                out[(size_t)m * strideM + (size_t)(b + 1) * strideB]       = acc[mi][nj][1];
                out[(size_t)(m + 8) * strideM + (size_t)b * strideB]       = acc[mi][nj][2];
                out[(size_t)(m + 8) * strideM + (size_t)(b + 1) * strideB] = acc[mi][nj][3];
            }
        }
}

// ---------------- fp16 single-term GEMM tile (hot path) ----------------
// out[m*64+b] = sum_k W[m][k] * Z[b][k]
__device__ __forceinline__ void gemm1(
    const __half* __restrict__ W,
    const __half* __restrict__ Z, int ldz,
    float* __restrict__ out,
    int K, int n0, int k0, int chunks, char* dsm)
{
    const int tid  = threadIdx.x;
    const int lane = tid & 31, wid = tid >> 5;
    const int wm = wid >> 2, wn = wid & 3;
    const uint32_t sb = smem_u32(dsm);

    float acc[2][2][4];
#pragma unroll
    for (int mi = 0; mi < 2; mi++)
#pragma unroll
        for (int nj = 0; nj < 2; nj++)
#pragma unroll
            for (int q = 0; q < 4; q++) acc[mi][nj][q] = 0.f;

    auto stage = [&](int c) {
        const uint32_t S = sb + (c & 1) * BUF1;
        const int kb = k0 + c * 128;
#pragma unroll
        for (int i = 0; i < 4; i++) {
            int idx = i * 512 + tid;
            int row = idx >> 4, cg = idx & 15;
            size_t g = (size_t)(n0 + row) * K + kb + cg * 8;
            cpa16(S + (row * PITCH + cg * 8) * 2, W + g);
        }
#pragma unroll
        for (int i = 0; i < 2; i++) {
            int idx = i * 512 + tid;
            int row = idx >> 4, cg = idx & 15;
            size_t g = (size_t)row * ldz + kb + cg * 8;
            cpa16(S + WBYTES + (row * PITCH + cg * 8) * 2, Z + g);
        }
        CP_COMMIT();
    };

    stage(0);
    for (int c = 0; c < chunks; c++) {
        if (c + 1 < chunks) {
            stage(c + 1);
            asm volatile("cp.async.wait_group 1;" ::: "memory");
        } else {
            asm volatile("cp.async.wait_group 0;" ::: "memory");
        }
        __syncthreads();

        const uint32_t S = sb + (c & 1) * BUF1;
        const uint32_t aw = S + ((wm * 32 + (lane & 15)) * PITCH + (lane >> 4) * 8) * 2;
        const uint32_t bz = S + WBYTES + ((wn * 16 + (lane & 15)) * PITCH + (lane >> 4) * 8) * 2;

#pragma unroll
        for (int ks = 0; ks < 8; ks++) {
            const uint32_t koff = ks * 32;
            uint32_t ah[2][4], bh[4];
#pragma unroll
            for (int mi = 0; mi < 2; mi++)
                ldm4(ah[mi], aw + mi * 16 * PITCH * 2 + koff);
            ldm4(bh, bz + koff);
#pragma unroll
            for (int mi = 0; mi < 2; mi++)
#pragma unroll
                for (int nj = 0; nj < 2; nj++)
                    mma_f16(acc[mi][nj], ah[mi], bh[nj], bh[2 + nj]);
        }
        __syncthreads();
    }

#pragma unroll
    for (int mi = 0; mi < 2; mi++)
#pragma unroll
        for (int nj = 0; nj < 2; nj++) {
            int m = n0 + wm * 32 + mi * 16 + (lane >> 2);
            int b = wn * 16 + nj * 8 + (lane & 3) * 2;
            __stcs((float2*)(out + (size_t)m * 64 + b),
                   make_float2(acc[mi][nj][0], acc[mi][nj][1]));
            __stcs((float2*)(out + (size_t)(m + 8) * 64 + b),
                   make_float2(acc[mi][nj][2], acc[mi][nj][3]));
        }
}

// ---------------- cell phase ----------------
__device__ __forceinline__ void cell_phase(
    int e, const float* __restrict__ part,
    const float* __restrict__ base, const float* __restrict__ bias,
    float* __restrict__ cT,
    __half* hA, int offA, __half* hB, int offB,
    float* __restrict__ h1f)
{
    int d = e >> 6, b = e & 63;
    float g[4];
#pragma unroll
    for (int j = 0; j < 4; j++) {
        float acc = bias[j * 1024 + d];
        if (base) acc += __ldcs(base + (size_t)j * 65536 + e);
#pragma unroll
        for (int ks = 0; ks < 4; ks++)
            acc += __ldcs(part + (size_t)ks * 262144 + (size_t)j * 65536 + e);
        g[j] = acc;
    }
    float ig = 1.f / (1.f + expf(-g[0]));
    float fg = 1.f / (1.f + expf(-g[1]));
    float gg = tanhf(g[2]);
    float og = 1.f / (1.f + expf(-g[3]));
    float cn = fg * cT[e] + ig * gg;
    float h  = og * tanhf(cn);
    cT[e] = cn;
    __half hv = __float2half_rn(h);
    hA[b * 2048 + offA + d] = hv;
    hB[b * 2048 + offB + d] = hv;
    if (h1f) h1f[b * 1024 + d] = h;
}

// ---------------- persistent kernel ----------------
__global__ void __launch_bounds__(512) persistent_k(
    float* __restrict__ outs, float* __restrict__ attns)
{
    extern __shared__ __align__(16) char dsm[];
    const int bi = blockIdx.x, tid = threadIdx.x;
    const int lane = tid & 31, w = tid >> 5;
    int tgt = g_release;

    for (int t = 0; t < 64; t++) {
        // ---- P1: LSTM0 GEMM: [feed|h0] K=2048; 32 mtiles x 4 ks, 4 chunks ----
        gemm1(g_Wc0H, g_Z0f, 2048,
              g_part + (size_t)(bi & 3) * 262144,
              2048, (bi >> 2) * 128, (bi & 3) * 512, 4, dsm);
        gsync(tgt, bi);
        // ---- P2: cell0 (adds precomputed embW base) ----
        cell_phase(bi * 512 + tid, g_part, g_embW + (size_t)t * 262144, g_bias0,
                   g_cT0, g_Z1f, 0, g_Z0f, 1024, nullptr);
        gsync(tgt, bi);
        // ---- P3: LSTM1 GEMM ----
        gemm1(g_Wc1H, g_Z1f, 2048,
              g_part + (size_t)(bi & 3) * 262144,
              2048, (bi >> 2) * 128, (bi & 3) * 512, 4, dsm);
        gsync(tgt, bi);
        // ---- P4: cell1 (h1 -> Z1f[:,1024:], also fp32 h1) ----
        cell_phase(bi * 512 + tid, g_part, nullptr, g_bias1,
                   g_cT1, g_Z1f, 1024, g_Z1f, 1024, g_h1f);
        gsync(tgt, bi);
        // ---- P5: CTAs 0-63 scores+softmax; CTAs 64-127 out-GEMM (h1 half, K=1024) ----
        if (bi < 64) {
            const int b = bi;
            float* qs = (float*)dsm;          // 1024 fp32 h1[b]
            float* sc = qs + 1024;            // 64 scores
            for (int d = tid; d < 1024; d += 512) qs[d] = g_h1f[b * 1024 + d];
            __syncthreads();
            const int bpair = b >> 1, brow = (b & 1) * 64;
#pragma unroll
            for (int so = 0; so < 4; so++) {
                int s = w * 4 + so;
                float acc = 0.f;
#pragma unroll
                for (int eblk = 0; eblk < 16; eblk++) {
                    const float* cwp = g_ctxWT +
                        ((size_t)(bpair * 16 + eblk) * 128 + brow + s) * 64;
                    acc += qs[eblk * 64 + lane] * cwp[lane];
                    acc += qs[eblk * 64 + 32 + lane] * cwp[32 + lane];
                }
#pragma unroll
                for (int off = 16; off; off >>= 1)
                    acc += __shfl_down_sync(0xffffffffu, acc, off);
                if (lane == 0) sc[s] = acc;
            }
            __syncthreads();
            if (tid < 32) {
                float v0 = sc[tid], v1 = sc[tid + 32];
                float m = fmaxf(v0, v1);
#pragma unroll
                for (int off = 16; off; off >>= 1)
                    m = fmaxf(m, __shfl_xor_sync(0xffffffffu, m, off));
                float e0 = expf(v0 - m), e1 = expf(v1 - m);
                float s = e0 + e1;
#pragma unroll
                for (int off = 16; off; off >>= 1)
                    s += __shfl_xor_sync(0xffffffffu, s, off);
                float inv = 1.f / s;
                float a0 = e0 * inv, a1 = e1 * inv;
                g_align[b * 64 + tid] = a0;
                g_align[b * 64 + tid + 32] = a1;
                float* at = attns + (size_t)t * 4096 + b * 64;
                __stcs(at + tid, a0);
                __stcs(at + tid + 32, a1);
            }
        } else {
            const int idx = bi - 64;                  // 0..63
            const int mt = idx >> 3, ks = idx & 7;    // 8 mtiles x 8 ksplits, 1 chunk
            gemm1(g_WoH1, g_Z1f + 1024, 2048,
                  g_part + (size_t)(16 + ks) * 65536,
                  1024, mt * 128, ks * 128, 1, dsm);
        }
        gsync(tgt, bi);
        // ---- P6: combine: y = sum_s align*ctxOut + sum_ks part; tanh; outputs+feed ----
        {
            float* salign = (float*)dsm;   // 64*64
            for (int i = tid; i < 4096; i += 512) salign[i] = g_align[i];
            __syncthreads();
            int e = bi * 512 + tid;
            int n = e >> 6, b = e & 63;
            float acc = 0.f;
#pragma unroll
            for (int ks = 0; ks < 8; ks++)
                acc += __ldcs(g_part + (size_t)(16 + ks) * 65536 + e);
            const float4* co = (const float4*)(g_ctxOut + (size_t)e * 64);
            const float* al = salign + b * 64;
#pragma unroll
            for (int sq = 0; sq < 16; sq++) {
                float4 v = co[sq];
                acc += al[sq * 4 + 0] * v.x + al[sq * 4 + 1] * v.y
                     + al[sq * 4 + 2] * v.z + al[sq * 4 + 3] * v.w;
            }
            float h = tanhf(acc);
            __stcs(outs + (size_t)t * 65536 + b * 1024 + n, h);
            g_Z0f[b * 2048 + n] = __float2half_rn(h);
        }
        gsync(tgt, bi);
    }
}

// ---------------- embW precompute: [t][n][b] = emb_t @ W0e^T (fp16 1-term) ----------------
__global__ void __launch_bounds__(512) gemm_pre(float* __restrict__ out)
{
    extern __shared__ __align__(16) char dsm[];
    gemm1(g_W0eH, g_embH + (size_t)blockIdx.y * 65536, 1024,
          out + (size_t)blockIdx.y * 262144,
          1024, blockIdx.x * 128, 0, 8, dsm);
}

// ---------------- ctxW precompute: scores matrix (bf16 3-term) ----------------
__global__ void __launch_bounds__(512) ctxw_pre(float* __restrict__ out)
{
    extern __shared__ __align__(16) char dsm[];
    const int bpair = blockIdx.x;   // 32
    const int eblk  = blockIdx.y;   // 16
    gemm3t(g_ctxRh + (size_t)bpair * 131072, g_ctxRl + (size_t)bpair * 131072,
           g_WinT_h + (size_t)eblk * 65536, g_WinT_l + (size_t)eblk * 65536, 1024,
           out + ((size_t)bpair * 16 + eblk) * 8192, 64, 1,
           1024, 0, 0, 8, dsm);
}

// ---------------- ctxOut precompute (bf16 3-term) ----------------
__global__ void __launch_bounds__(512) ctxout_pre(float* __restrict__ out)
{
    extern __shared__ __align__(16) char dsm[];
    const int mt = blockIdx.x;   // 8
    const int s  = blockIdx.y;   // 64
    gemm3t(g_Wout_h, g_Wout_l,
           g_ctxPh + (size_t)s * 65536, g_ctxPl + (size_t)s * 65536, 1024,
           out + s, 4096, 64,
           2048, mt * 128, 0, 8, dsm);
}

// ---------------- init state ----------------
__global__ void init_state(const float* __restrict__ input_feed,
                           const float* __restrict__ h0, const float* __restrict__ c0)
{
    int e = blockIdx.x * blockDim.x + threadIdx.x;  // 65536
    int b = e >> 10, d = e & 1023;
    g_Z0f[b * 2048 + d] = __float2half_rn(input_feed[e]);
    g_Z0f[b * 2048 + 1024 + d] = __float2half_rn(h0[e]);
    g_Z1f[b * 2048 + 1024 + d] = __float2half_rn(h0[65536 + e]);
    g_cT0[d * 64 + b] = c0[e];
    g_cT1[d * 64 + b] = c0[65536 + e];
}

// ---------------- weight prep ----------------
__global__ void prep_w(const float* __restrict__ W_ih0, const float* __restrict__ W_hh0,
                       const float* __restrict__ W_ih1, const float* __restrict__ W_hh1,
                       const float* __restrict__ W_in,  const float* __restrict__ W_out,
                       const float* __restrict__ emb,   const float* __restrict__ ctx,
                       const float* __restrict__ b_ih0, const float* __restrict__ b_hh0,
                       const float* __restrict__ b_ih1, const float* __restrict__ b_hh1)
{
    size_t stride = (size_t)gridDim.x * blockDim.x;
    for (size_t i = (size_t)blockIdx.x * blockDim.x + threadIdx.x;
         i < 4096ull * 2048ull; i += stride) {
        size_t n = i >> 11, k = i & 2047;
        float v0 = (k < 1024) ? W_ih0[n * 2048 + 1024 + k] : W_hh0[n * 1024 + (k - 1024)];
        g_Wc0H[i] = __float2half_rn(v0);
        float v1 = (k < 1024) ? W_ih1[n * 1024 + k] : W_hh1[n * 1024 + (k - 1024)];
        g_Wc1H[i] = __float2half_rn(v1);
        if (n < 1024) {
            hilo(W_out[i], g_Wout_h[i], g_Wout_l[i]);           // bf16 for ctxout_pre
            if (k >= 1024)
                g_WoH1[n * 1024 + (k - 1024)] = __float2half_rn(W_out[i]);
        }
        if (i < 4096ull * 1024ull) {
            size_t nn = i >> 10, kk = i & 1023;
            g_W0eH[i] = __float2half_rn(W_ih0[nn * 2048 + kk]);
            g_embH[i] = __float2half_rn(emb[i]);
            hilo(ctx[i], g_ctxPh[i], g_ctxPl[i]);
            size_t b = (i >> 10) & 63, s = i >> 16, d = i & 1023;
            size_t ri = ((b >> 1) * 128 + (b & 1) * 64 + s) * 1024 + d;
            hilo(ctx[i], g_ctxRh[ri], g_ctxRl[ri]);
        }
        if (i < 1024ull * 1024ull) {
            size_t ti = (i & 1023) * 1024 + (i >> 10);
            hilo(W_in[i], g_WinT_h[ti], g_WinT_l[ti]);
        }
        if (i < 4096) {
            g_bias0[i] = b_ih0[i] + b_hh0[i];
            g_bias1[i] = b_ih1[i] + b_hh1[i];
        }
    }
}

// ---------------- host orchestration ----------------
extern "C" void kernel_launch(void* const* d_in, const int* in_sizes, int n_in,
                              void* d_out, int out_size)
{
    (void)in_sizes; (void)n_in; (void)out_size;
    const float* emb        = (const float*)d_in[0];
    const float* context    = (const float*)d_in[1];
    const float* input_feed = (const float*)d_in[2];
    const float* h0         = (const float*)d_in[3];
    const float* c0         = (const float*)d_in[4];
    const float* W_ih0      = (const float*)d_in[5];
    const float* W_hh0      = (const float*)d_in[6];
    const float* b_ih0      = (const float*)d_in[7];
    const float* b_hh0      = (const float*)d_in[8];
    const float* W_ih1      = (const float*)d_in[9];
    const float* W_hh1      = (const float*)d_in[10];
    const float* b_ih1      = (const float*)d_in[11];
    const float* b_hh1      = (const float*)d_in[12];
    const float* W_in       = (const float*)d_in[13];
    const float* W_out      = (const float*)d_in[14];

    float* outs  = (float*)d_out;
    float* attns = outs + 64 * 64 * 1024;

    static bool attr_set = false;
    if (!attr_set) {
        cudaFuncSetAttribute(persistent_k, cudaFuncAttributeMaxDynamicSharedMemorySize, GEMM_SMEM);
        cudaFuncSetAttribute(gemm_pre, cudaFuncAttributeMaxDynamicSharedMemorySize, GEMM_SMEM);
        cudaFuncSetAttribute(ctxw_pre, cudaFuncAttributeMaxDynamicSharedMemorySize, GEMM_SMEM);
        cudaFuncSetAttribute(ctxout_pre, cudaFuncAttributeMaxDynamicSharedMemorySize, GEMM_SMEM);
        attr_set = true;
    }

    float *pEmbW, *pCtxWT, *pCtxOut;
    cudaGetSymbolAddress((void**)&pEmbW, g_embW);
    cudaGetSymbolAddress((void**)&pCtxWT, g_ctxWT);
    cudaGetSymbolAddress((void**)&pCtxOut, g_ctxOut);

    prep_w<<<4096, 256>>>(W_ih0, W_hh0, W_ih1, W_hh1, W_in, W_out, emb, context,
                          b_ih0, b_hh0, b_ih1, b_hh1);
    init_state<<<256, 256>>>(input_feed, h0, c0);
    ctxw_pre<<<dim3(32, 16), 512, GEMM_SMEM>>>(pCtxWT);
    ctxout_pre<<<dim3(8, 64), 512, GEMM_SMEM>>>(pCtxOut);
    gemm_pre<<<dim3(32, 64), 512, GEMM_SMEM>>>(pEmbW);
    persistent_k<<<NCTA, 512, GEMM_SMEM>>>(outs, attns);
}

// round 15
// speedup vs baseline: 1.7288x; 1.1268x over previous
#include <cuda_runtime.h>
#include <cuda_fp16.h>
#include <cstdint>
#include <math.h>

// Shapes: T=64, B=64, S=64, E=1024, D=1024, G=4096
// Persistent kernel: 128 CTAs x 512 threads, one CTA per SM, 6 fast barriers/step.
// ALL GEMMs single-term fp16 (mma.sync m16n8k16 f16->f32). Precomputed tensors
// (ctxWT scores matrix, ctxOut output linearization, embW) stored fp16.
// attn_h = tanh( sum_s align[s]*ctxOut[s,b,:] + Wout[:,1024:] . h1 ).

#define NCTA 128

// ---------------- static device scratch ----------------
__device__ __align__(16) __half g_W0eH[4096*1024];   // W_ih0[:, :1024]
__device__ __align__(16) __half g_Wc0H[4096*2048];   // [W_ih0[:,1024:] | W_hh0]
__device__ __align__(16) __half g_Wc1H[4096*2048];   // [W_ih1 | W_hh1]
__device__ __align__(16) __half g_WoutF[1024*2048];  // full W_out
__device__ __align__(16) __half g_embH[4096*1024];   // emb rows (t*64+b)
__device__ __align__(16) __half g_ctxRf[4096*1024];  // ctx repacked per bpair
__device__ __align__(16) __half g_ctxPf[4096*1024];  // ctx plain [(s*64+b)][d]
__device__ __align__(16) __half g_WinTf[1024*1024];  // W_in^T: [e][d]
__device__ __align__(16) __half g_ctxWTh[64*64*1024];// [(bpair*16+eblk)][srow(128)][elocal(64)]
__device__ __align__(16) __half g_ctxOutH[1024*64*64];// [(n*64+b)][s]
__device__ __align__(16) __half g_embWh[64*4096*64]; // [t][n][b]
__device__ __align__(16) float g_part[24*1024*64];   // split-K partials
__device__ __align__(16) __half g_Z0f[64*2048];      // [feed | h0_prev]
__device__ __align__(16) __half g_Z1f[64*2048];      // [h0_new | h1]
__device__ __align__(16) float g_h1f[64*1024];       // fp32 h1 [b][d]
__device__ __align__(16) float g_align[64*64];       // align [b][s]
__device__ __align__(16) float g_cT0[1024*64], g_cT1[1024*64];
__device__ __align__(16) float g_bias0[4096], g_bias1[4096];
__device__ volatile int g_arrive[NCTA];
__device__ volatile int g_release;

// ---------------- PTX helpers ----------------
__device__ __forceinline__ uint32_t smem_u32(const void* p) {
    uint32_t a;
    asm("{ .reg .u64 t; cvta.to.shared.u64 t, %1; cvt.u32.u64 %0, t; }" : "=r"(a) : "l"(p));
    return a;
}
__device__ __forceinline__ void ldm4(uint32_t* r, uint32_t a) {
    asm volatile("ldmatrix.sync.aligned.m8n8.x4.shared.b16 {%0,%1,%2,%3}, [%4];"
                 : "=r"(r[0]), "=r"(r[1]), "=r"(r[2]), "=r"(r[3]) : "r"(a));
}
__device__ __forceinline__ void mma_f16(float* c, const uint32_t* a, uint32_t b0, uint32_t b1) {
    asm volatile("mma.sync.aligned.m16n8k16.row.col.f32.f16.f16.f32 "
                 "{%0,%1,%2,%3}, {%4,%5,%6,%7}, {%8,%9}, {%0,%1,%2,%3};"
                 : "+f"(c[0]), "+f"(c[1]), "+f"(c[2]), "+f"(c[3])
                 : "r"(a[0]), "r"(a[1]), "r"(a[2]), "r"(a[3]), "r"(b0), "r"(b1));
}
__device__ __forceinline__ void cpa16(uint32_t s, const void* g) {
    asm volatile("cp.async.cg.shared.global [%0], [%1], 16;" :: "r"(s), "l"(g));
}
#define CP_COMMIT() asm volatile("cp.async.commit_group;" ::: "memory")

// fast global barrier: per-CTA arrive flags + CTA0 scan + release word
__device__ __forceinline__ void gsync(int& tgt, int bi) {
    __syncthreads();
    tgt++;
    if (threadIdx.x == 0) { __threadfence(); g_arrive[bi] = tgt; }
    if (bi == 0) {
        if (threadIdx.x < NCTA) {
            while (g_arrive[threadIdx.x] - tgt < 0) {}
        }
        __syncthreads();
        if (threadIdx.x == 0) { __threadfence(); g_release = tgt; }
    } else {
        if (threadIdx.x == 0) {
            while (g_release - tgt < 0) {}
            __threadfence();
        }
    }
    __syncthreads();
}

// ---------------- tile constants (Kchunk=128) ----------------
static constexpr int PITCH = 136;                   // 16-bit elems; 272B rows
static constexpr int WBYTES = 128 * PITCH * 2;      // 34816
static constexpr int ZBYTES = 64 * PITCH * 2;       // 17408
static constexpr int BUF1 = WBYTES + ZBYTES;        // 52224
static constexpr int GEMM_SMEM = 2 * BUF1;          // 104448

// ---------------- fp16 single-term GEMM tile (512 threads, 4x4 warp grid) ----------------
// out[m][b] = sum_k W[m][k] * Z[b][k]; K doubles as W leading dim.
// OUTH=false: fp32 out, strideB must be 1. OUTH=true: fp16 out; strideB==1 uses
// half2 stores, else scalar scatter (strideM/strideB in half elems).
template <bool OUTH>
__device__ __forceinline__ void gemm1(
    const __half* __restrict__ W,
    const __half* __restrict__ Z, int ldz,
    void* __restrict__ outv, size_t strideM, int strideB,
    int K, int n0, int k0, int chunks, char* dsm)
{
    const int tid  = threadIdx.x;
    const int lane = tid & 31, wid = tid >> 5;
    const int wm = wid >> 2, wn = wid & 3;
    const uint32_t sb = smem_u32(dsm);

    float acc[2][2][4];
#pragma unroll
    for (int mi = 0; mi < 2; mi++)
#pragma unroll
        for (int nj = 0; nj < 2; nj++)
#pragma unroll
            for (int q = 0; q < 4; q++) acc[mi][nj][q] = 0.f;

    auto stage = [&](int c) {
        const uint32_t S = sb + (c & 1) * BUF1;
        const int kb = k0 + c * 128;
#pragma unroll
        for (int i = 0; i < 4; i++) {
            int idx = i * 512 + tid;
            int row = idx >> 4, cg = idx & 15;
            size_t g = (size_t)(n0 + row) * K + kb + cg * 8;
            cpa16(S + (row * PITCH + cg * 8) * 2, W + g);
        }
#pragma unroll
        for (int i = 0; i < 2; i++) {
            int idx = i * 512 + tid;
            int row = idx >> 4, cg = idx & 15;
            size_t g = (size_t)row * ldz + kb + cg * 8;
            cpa16(S + WBYTES + (row * PITCH + cg * 8) * 2, Z + g);
        }
        CP_COMMIT();
    };

    stage(0);
    for (int c = 0; c < chunks; c++) {
        if (c + 1 < chunks) {
            stage(c + 1);
            asm volatile("cp.async.wait_group 1;" ::: "memory");
        } else {
            asm volatile("cp.async.wait_group 0;" ::: "memory");
        }
        __syncthreads();

        const uint32_t S = sb + (c & 1) * BUF1;
        const uint32_t aw = S + ((wm * 32 + (lane & 15)) * PITCH + (lane >> 4) * 8) * 2;
        const uint32_t bz = S + WBYTES + ((wn * 16 + (lane & 15)) * PITCH + (lane >> 4) * 8) * 2;

#pragma unroll
        for (int ks = 0; ks < 8; ks++) {
            const uint32_t koff = ks * 32;
            uint32_t ah[2][4], bh[4];
#pragma unroll
            for (int mi = 0; mi < 2; mi++)
                ldm4(ah[mi], aw + mi * 16 * PITCH * 2 + koff);
            ldm4(bh, bz + koff);
#pragma unroll
            for (int mi = 0; mi < 2; mi++)
#pragma unroll
                for (int nj = 0; nj < 2; nj++)
                    mma_f16(acc[mi][nj], ah[mi], bh[nj], bh[2 + nj]);
        }
        __syncthreads();
    }

#pragma unroll
    for (int mi = 0; mi < 2; mi++)
#pragma unroll
        for (int nj = 0; nj < 2; nj++) {
            int m = n0 + wm * 32 + mi * 16 + (lane >> 2);
            int b = wn * 16 + nj * 8 + (lane & 3) * 2;
            if (!OUTH) {
                float* out = (float*)outv;
                __stcs((float2*)(out + (size_t)m * strideM + b),
                       make_float2(acc[mi][nj][0], acc[mi][nj][1]));
                __stcs((float2*)(out + (size_t)(m + 8) * strideM + b),
                       make_float2(acc[mi][nj][2], acc[mi][nj][3]));
            } else {
                __half* out = (__half*)outv;
                if (strideB == 1) {
                    *(__half2*)(out + (size_t)m * strideM + b) =
                        __floats2half2_rn(acc[mi][nj][0], acc[mi][nj][1]);
                    *(__half2*)(out + (size_t)(m + 8) * strideM + b) =
                        __floats2half2_rn(acc[mi][nj][2], acc[mi][nj][3]);
                } else {
                    out[(size_t)m * strideM + (size_t)b * strideB]             = __float2half_rn(acc[mi][nj][0]);
                    out[(size_t)m * strideM + (size_t)(b + 1) * strideB]       = __float2half_rn(acc[mi][nj][1]);
                    out[(size_t)(m + 8) * strideM + (size_t)b * strideB]       = __float2half_rn(acc[mi][nj][2]);
                    out[(size_t)(m + 8) * strideM + (size_t)(b + 1) * strideB] = __float2half_rn(acc[mi][nj][3]);
                }
            }
        }
}

// ---------------- cell phase ----------------
__device__ __forceinline__ void cell_phase(
    int e, const float* __restrict__ part,
    const __half* __restrict__ base, const float* __restrict__ bias,
    float* __restrict__ cT,
    __half* hA, int offA, __half* hB, int offB,
    float* __restrict__ h1f)
{
    int d = e >> 6, b = e & 63;
    float g[4];
#pragma unroll
    for (int j = 0; j < 4; j++) {
        float acc = bias[j * 1024 + d];
        if (base) acc += __half2float(base[(size_t)j * 65536 + e]);
#pragma unroll
        for (int ks = 0; ks < 4; ks++)
            acc += __ldcs(part + (size_t)ks * 262144 + (size_t)j * 65536 + e);
        g[j] = acc;
    }
    float ig = 1.f / (1.f + expf(-g[0]));
    float fg = 1.f / (1.f + expf(-g[1]));
    float gg = tanhf(g[2]);
    float og = 1.f / (1.f + expf(-g[3]));
    float cn = fg * cT[e] + ig * gg;
    float h  = og * tanhf(cn);
    cT[e] = cn;
    __half hv = __float2half_rn(h);
    hA[b * 2048 + offA + d] = hv;
    hB[b * 2048 + offB + d] = hv;
    if (h1f) h1f[b * 1024 + d] = h;
}

// ---------------- persistent kernel ----------------
__global__ void __launch_bounds__(512) persistent_k(
    float* __restrict__ outs, float* __restrict__ attns)
{
    extern __shared__ __align__(16) char dsm[];
    const int bi = blockIdx.x, tid = threadIdx.x;
    const int lane = tid & 31, w = tid >> 5;
    int tgt = g_release;

    for (int t = 0; t < 64; t++) {
        // ---- P1: LSTM0 GEMM: [feed|h0] K=2048; 32 mtiles x 4 ks, 4 chunks ----
        gemm1<false>(g_Wc0H, g_Z0f, 2048,
                     g_part + (size_t)(bi & 3) * 262144, 64, 1,
                     2048, (bi >> 2) * 128, (bi & 3) * 512, 4, dsm);
        gsync(tgt, bi);
        // ---- P2: cell0 (adds precomputed fp16 embW base) ----
        cell_phase(bi * 512 + tid, g_part, g_embWh + (size_t)t * 262144, g_bias0,
                   g_cT0, g_Z1f, 0, g_Z0f, 1024, nullptr);
        gsync(tgt, bi);
        // ---- P3: LSTM1 GEMM ----
        gemm1<false>(g_Wc1H, g_Z1f, 2048,
                     g_part + (size_t)(bi & 3) * 262144, 64, 1,
                     2048, (bi >> 2) * 128, (bi & 3) * 512, 4, dsm);
        gsync(tgt, bi);
        // ---- P4: cell1 (h1 -> Z1f[:,1024:], also fp32 h1) ----
        cell_phase(bi * 512 + tid, g_part, nullptr, g_bias1,
                   g_cT1, g_Z1f, 1024, g_Z1f, 1024, g_h1f);
        gsync(tgt, bi);
        // ---- P5: CTAs 0-63 scores+softmax; CTAs 64-127 out-GEMM (h1 half) ----
        if (bi < 64) {
            const int b = bi;
            float* qs = (float*)dsm;          // 1024 fp32 h1[b]
            float* sc = qs + 1024;            // 64 scores
            for (int d = tid; d < 1024; d += 512) qs[d] = g_h1f[b * 1024 + d];
            __syncthreads();
            const int bpair = b >> 1, brow = (b & 1) * 64;
#pragma unroll
            for (int so = 0; so < 4; so++) {
                int s = w * 4 + so;
                float acc = 0.f;
#pragma unroll
                for (int eblk = 0; eblk < 16; eblk++) {
                    const __half2* cwp = (const __half2*)(g_ctxWTh +
                        ((size_t)(bpair * 16 + eblk) * 128 + brow + s) * 64);
                    float2 cf = __half22float2(cwp[lane]);
                    float2 q2 = *(const float2*)(qs + eblk * 64 + 2 * lane);
                    acc += q2.x * cf.x + q2.y * cf.y;
                }
#pragma unroll
                for (int off = 16; off; off >>= 1)
                    acc += __shfl_down_sync(0xffffffffu, acc, off);
                if (lane == 0) sc[s] = acc;
            }
            __syncthreads();
            if (tid < 32) {
                float v0 = sc[tid], v1 = sc[tid + 32];
                float m = fmaxf(v0, v1);
#pragma unroll
                for (int off = 16; off; off >>= 1)
                    m = fmaxf(m, __shfl_xor_sync(0xffffffffu, m, off));
                float e0 = expf(v0 - m), e1 = expf(v1 - m);
                float s = e0 + e1;
#pragma unroll
                for (int off = 16; off; off >>= 1)
                    s += __shfl_xor_sync(0xffffffffu, s, off);
                float inv = 1.f / s;
                float a0 = e0 * inv, a1 = e1 * inv;
                g_align[b * 64 + tid] = a0;
                g_align[b * 64 + tid + 32] = a1;
                float* at = attns + (size_t)t * 4096 + b * 64;
                __stcs(at + tid, a0);
                __stcs(at + tid + 32, a1);
            }
        } else {
            const int idx = bi - 64;                  // 0..63
            const int mt = idx >> 3, ks = idx & 7;    // 8 mtiles x 8 ksplits, 1 chunk
            gemm1<false>(g_WoutF, g_Z1f, 2048,
                         g_part + (size_t)(16 + ks) * 65536, 64, 1,
                         2048, mt * 128, 1024 + ks * 128, 1, dsm);
        }
        gsync(tgt, bi);
        // ---- P6: combine: y = sum_s align*ctxOutH + sum_ks part; tanh; outputs+feed ----
        {
            float* salign = (float*)dsm;   // 64*64
            for (int i = tid; i < 4096; i += 512) salign[i] = g_align[i];
            __syncthreads();
            int e = bi * 512 + tid;
            int n = e >> 6, b = e & 63;
            float acc = 0.f;
#pragma unroll
            for (int ks = 0; ks < 8; ks++)
                acc += __ldcs(g_part + (size_t)(16 + ks) * 65536 + e);
            const uint4* co = (const uint4*)(g_ctxOutH + (size_t)e * 64);
            const float* al = salign + b * 64;
#pragma unroll
            for (int sq = 0; sq < 8; sq++) {       // 8 x uint4 = 64 halfs
                uint4 u = co[sq];
                float2 v0 = __half22float2(*(const __half2*)&u.x);
                float2 v1 = __half22float2(*(const __half2*)&u.y);
                float2 v2 = __half22float2(*(const __half2*)&u.z);
                float2 v3 = __half22float2(*(const __half2*)&u.w);
                const float* a8 = al + sq * 8;
                acc += a8[0] * v0.x + a8[1] * v0.y + a8[2] * v1.x + a8[3] * v1.y
                     + a8[4] * v2.x + a8[5] * v2.y + a8[6] * v3.x + a8[7] * v3.y;
            }
            float h = tanhf(acc);
            __stcs(outs + (size_t)t * 65536 + b * 1024 + n, h);
            g_Z0f[b * 2048 + n] = __float2half_rn(h);
        }
        gsync(tgt, bi);
    }
}

// ---------------- embW precompute: [t][n][b] = emb_t @ W0e^T (fp16 out) ----------------
__global__ void __launch_bounds__(512) gemm_pre()
{
    extern __shared__ __align__(16) char dsm[];
    gemm1<true>(g_W0eH, g_embH + (size_t)blockIdx.y * 65536, 1024,
                g_embWh + (size_t)blockIdx.y * 262144, 64, 1,
                1024, blockIdx.x * 128, 0, 8, dsm);
}

// ---------------- ctxW precompute: scores matrix (fp16) ----------------
__global__ void __launch_bounds__(512) ctxw_pre()
{
    extern __shared__ __align__(16) char dsm[];
    const int bpair = blockIdx.x;   // 32
    const int eblk  = blockIdx.y;   // 16
    gemm1<true>(g_ctxRf + (size_t)bpair * 131072,
                g_WinTf + (size_t)eblk * 65536, 1024,
                g_ctxWTh + ((size_t)bpair * 16 + eblk) * 8192, 64, 1,
                1024, 0, 0, 8, dsm);
}

// ---------------- ctxOut precompute: [(n*64+b)][s] = Wout_cvec . ctx[s,b] (fp16) ----------------
__global__ void __launch_bounds__(512) ctxout_pre()
{
    extern __shared__ __align__(16) char dsm[];
    const int mt = blockIdx.x;   // 8
    const int s  = blockIdx.y;   // 64
    gemm1<true>(g_WoutF, g_ctxPf + (size_t)s * 65536, 1024,
                g_ctxOutH + s, 4096, 64,
                2048, mt * 128, 0, 8, dsm);
}

// ---------------- init state ----------------
__global__ void init_state(const float* __restrict__ input_feed,
                           const float* __restrict__ h0, const float* __restrict__ c0)
{
    int e = blockIdx.x * blockDim.x + threadIdx.x;  // 65536
    int b = e >> 10, d = e & 1023;
    g_Z0f[b * 2048 + d] = __float2half_rn(input_feed[e]);
    g_Z0f[b * 2048 + 1024 + d] = __float2half_rn(h0[e]);
    g_Z1f[b * 2048 + 1024 + d] = __float2half_rn(h0[65536 + e]);
    g_cT0[d * 64 + b] = c0[e];
    g_cT1[d * 64 + b] = c0[65536 + e];
}

// ---------------- weight prep ----------------
__global__ void prep_w(const float* __restrict__ W_ih0, const float* __restrict__ W_hh0,
                       const float* __restrict__ W_ih1, const float* __restrict__ W_hh1,
                       const float* __restrict__ W_in,  const float* __restrict__ W_out,
                       const float* __restrict__ emb,   const float* __restrict__ ctx,
                       const float* __restrict__ b_ih0, const float* __restrict__ b_hh0,
                       const float* __restrict__ b_ih1, const float* __restrict__ b_hh1)
{
    size_t stride = (size_t)gridDim.x * blockDim.x;
    for (size_t i = (size_t)blockIdx.x * blockDim.x + threadIdx.x;
         i < 4096ull * 2048ull; i += stride) {
        size_t n = i >> 11, k = i & 2047;
        float v0 = (k < 1024) ? W_ih0[n * 2048 + 1024 + k] : W_hh0[n * 1024 + (k - 1024)];
        g_Wc0H[i] = __float2half_rn(v0);
        float v1 = (k < 1024) ? W_ih1[n * 1024 + k] : W_hh1[n * 1024 + (k - 1024)];
        g_Wc1H[i] = __float2half_rn(v1);
        if (n < 1024) g_WoutF[i] = __float2half_rn(W_out[i]);
        if (i < 4096ull * 1024ull) {
            size_t nn = i >> 10, kk = i & 1023;
            g_W0eH[i] = __float2half_rn(W_ih0[nn * 2048 + kk]);
            g_embH[i] = __float2half_rn(emb[i]);
            g_ctxPf[i] = __float2half_rn(ctx[i]);
            size_t b = (i >> 10) & 63, s = i >> 16, d = i & 1023;
            size_t ri = ((b >> 1) * 128 + (b & 1) * 64 + s) * 1024 + d;
            g_ctxRf[ri] = __float2half_rn(ctx[i]);
        }
        if (i < 1024ull * 1024ull) {
            size_t ti = (i & 1023) * 1024 + (i >> 10);
            g_WinTf[ti] = __float2half_rn(W_in[i]);
        }
        if (i < 4096) {
            g_bias0[i] = b_ih0[i] + b_hh0[i];
            g_bias1[i] = b_ih1[i] + b_hh1[i];
        }
    }
}

// ---------------- host orchestration ----------------
extern "C" void kernel_launch(void* const* d_in, const int* in_sizes, int n_in,
                              void* d_out, int out_size)
{
    (void)in_sizes; (void)n_in; (void)out_size;
    const float* emb        = (const float*)d_in[0];
    const float* context    = (const float*)d_in[1];
    const float* input_feed = (const float*)d_in[2];
    const float* h0         = (const float*)d_in[3];
    const float* c0         = (const float*)d_in[4];
    const float* W_ih0      = (const float*)d_in[5];
    const float* W_hh0      = (const float*)d_in[6];
    const float* b_ih0      = (const float*)d_in[7];
    const float* b_hh0      = (const float*)d_in[8];
    const float* W_ih1      = (const float*)d_in[9];
    const float* W_hh1      = (const float*)d_in[10];
    const float* b_ih1      = (const float*)d_in[11];
    const float* b_hh1      = (const float*)d_in[12];
    const float* W_in       = (const float*)d_in[13];
    const float* W_out      = (const float*)d_in[14];

    float* outs  = (float*)d_out;
    float* attns = outs + 64 * 64 * 1024;

    static bool attr_set = false;
    if (!attr_set) {
        cudaFuncSetAttribute(persistent_k, cudaFuncAttributeMaxDynamicSharedMemorySize, GEMM_SMEM);
        cudaFuncSetAttribute(gemm_pre, cudaFuncAttributeMaxDynamicSharedMemorySize, GEMM_SMEM);
        cudaFuncSetAttribute(ctxw_pre, cudaFuncAttributeMaxDynamicSharedMemorySize, GEMM_SMEM);
        cudaFuncSetAttribute(ctxout_pre, cudaFuncAttributeMaxDynamicSharedMemorySize, GEMM_SMEM);
        attr_set = true;
    }

    prep_w<<<4096, 256>>>(W_ih0, W_hh0, W_ih1, W_hh1, W_in, W_out, emb, context,
                          b_ih0, b_hh0, b_ih1, b_hh1);
    init_state<<<256, 256>>>(input_feed, h0, c0);
    ctxw_pre<<<dim3(32, 16), 512, GEMM_SMEM>>>();
    ctxout_pre<<<dim3(8, 64), 512, GEMM_SMEM>>>();
    gemm_pre<<<dim3(32, 64), 512, GEMM_SMEM>>>();
    persistent_k<<<NCTA, 512, GEMM_SMEM>>>(outs, attns);
}

// round 16
// speedup vs baseline: 1.8236x; 1.0548x over previous
#include <cuda_runtime.h>
#include <cuda_fp16.h>
#include <cstdint>
#include <math.h>

// Shapes: T=64, B=64, S=64, E=1024, D=1024, G=4096
// Persistent kernel: 128 CTAs x 512 threads, one CTA per SM.
// ALL GEMMs single-term fp16 (mma.sync m16n8k16 f16->f32).
// Gate-interleaved weight rows (n' = d*4 + gate) let the LSTM cell fuse into the
// layer-GEMM phase behind a 4-CTA mini-barrier: 4 phases + 4 global barriers/step.
// attn_h = tanh( sum_s align[s]*ctxOut[s,b,:] + Wout[:,1024:] . h1 ).

#define NCTA 128

// ---------------- static device scratch ----------------
__device__ __align__(16) __half g_W0eH[4096*1024];   // W_ih0[:, :1024], rows n'
__device__ __align__(16) __half g_Wc0H[4096*2048];   // [W_ih0[:,1024:] | W_hh0], rows n'
__device__ __align__(16) __half g_Wc1H[4096*2048];   // [W_ih1 | W_hh1], rows n'
__device__ __align__(16) __half g_WoutF[1024*2048];  // full W_out (natural rows)
__device__ __align__(16) __half g_embH[4096*1024];   // emb rows (t*64+b)
__device__ __align__(16) __half g_ctxRf[4096*1024];  // ctx repacked per bpair
__device__ __align__(16) __half g_ctxPf[4096*1024];  // ctx plain [(s*64+b)][d]
__device__ __align__(16) __half g_WinTf[1024*1024];  // W_in^T: [e][d]
__device__ __align__(16) __half g_ctxWTh[64*64*1024];// [(bpair*16+eblk)][srow(128)][elocal(64)]
__device__ __align__(16) __half g_ctxOutH[1024*64*64];// [(n*64+b)][s]
__device__ __align__(16) __half g_embWh[64*4096*64]; // [t][n'][b]
__device__ __align__(16) float g_part[24*1024*64];   // split-K partials
__device__ __align__(16) __half g_Z0f[64*2048];      // [feed | h0_prev]
__device__ __align__(16) __half g_Z1f[64*2048];      // [h0_new | h1]
__device__ __align__(16) float g_h1f[64*1024];       // fp32 h1 [b][d]
__device__ __align__(16) float g_align[64*64];       // align [b][s]
__device__ __align__(16) float g_cT0[1024*64], g_cT1[1024*64];
__device__ __align__(16) float g_bias0[4096], g_bias1[4096];  // reordered n'
__device__ volatile int g_arrive[NCTA];
__device__ volatile int g_release;
__device__ int g_mcnt[32];                           // per-mtile mini counters

// ---------------- PTX helpers ----------------
__device__ __forceinline__ uint32_t smem_u32(const void* p) {
    uint32_t a;
    asm("{ .reg .u64 t; cvta.to.shared.u64 t, %1; cvt.u32.u64 %0, t; }" : "=r"(a) : "l"(p));
    return a;
}
__device__ __forceinline__ void ldm4(uint32_t* r, uint32_t a) {
    asm volatile("ldmatrix.sync.aligned.m8n8.x4.shared.b16 {%0,%1,%2,%3}, [%4];"
                 : "=r"(r[0]), "=r"(r[1]), "=r"(r[2]), "=r"(r[3]) : "r"(a));
}
__device__ __forceinline__ void mma_f16(float* c, const uint32_t* a, uint32_t b0, uint32_t b1) {
    asm volatile("mma.sync.aligned.m16n8k16.row.col.f32.f16.f16.f32 "
                 "{%0,%1,%2,%3}, {%4,%5,%6,%7}, {%8,%9}, {%0,%1,%2,%3};"
                 : "+f"(c[0]), "+f"(c[1]), "+f"(c[2]), "+f"(c[3])
                 : "r"(a[0]), "r"(a[1]), "r"(a[2]), "r"(a[3]), "r"(b0), "r"(b1));
}
__device__ __forceinline__ void cpa16(uint32_t s, const void* g) {
    asm volatile("cp.async.cg.shared.global [%0], [%1], 16;" :: "r"(s), "l"(g));
}
#define CP_COMMIT() asm volatile("cp.async.commit_group;" ::: "memory")

// fast global barrier: per-CTA arrive flags + CTA0 scan + release word
__device__ __forceinline__ void gsync(int& tgt, int bi) {
    __syncthreads();
    tgt++;
    if (threadIdx.x == 0) { __threadfence(); g_arrive[bi] = tgt; }
    if (bi == 0) {
        if (threadIdx.x < NCTA) {
            while (g_arrive[threadIdx.x] - tgt < 0) {}
        }
        __syncthreads();
        if (threadIdx.x == 0) { __threadfence(); g_release = tgt; }
    } else {
        if (threadIdx.x == 0) {
            while (g_release - tgt < 0) {}
            __threadfence();
        }
    }
    __syncthreads();
}

// 4-CTA mini-barrier per mtile (monotonic counter; reset at kernel end)
__device__ __forceinline__ void msync(int mt, int& mtgt) {
    __syncthreads();
    mtgt += 4;
    if (threadIdx.x == 0) {
        __threadfence();
        atomicAdd(&g_mcnt[mt], 1);
        while (*(volatile int*)&g_mcnt[mt] - mtgt < 0) {}
        __threadfence();
    }
    __syncthreads();
}

// ---------------- tile constants (Kchunk=128) ----------------
static constexpr int PITCH = 136;                   // 16-bit elems; 272B rows
static constexpr int WBYTES = 128 * PITCH * 2;      // 34816
static constexpr int ZBYTES = 64 * PITCH * 2;       // 17408
static constexpr int BUF1 = WBYTES + ZBYTES;        // 52224
static constexpr int GEMM_SMEM = 2 * BUF1;          // 104448

// ---------------- fp16 single-term GEMM tile (512 threads, 4x4 warp grid) ----------------
template <bool OUTH>
__device__ __forceinline__ void gemm1(
    const __half* __restrict__ W,
    const __half* __restrict__ Z, int ldz,
    void* __restrict__ outv, size_t strideM, int strideB,
    int K, int n0, int k0, int chunks, char* dsm)
{
    const int tid  = threadIdx.x;
    const int lane = tid & 31, wid = tid >> 5;
    const int wm = wid >> 2, wn = wid & 3;
    const uint32_t sb = smem_u32(dsm);

    float acc[2][2][4];
#pragma unroll
    for (int mi = 0; mi < 2; mi++)
#pragma unroll
        for (int nj = 0; nj < 2; nj++)
#pragma unroll
            for (int q = 0; q < 4; q++) acc[mi][nj][q] = 0.f;

    auto stage = [&](int c) {
        const uint32_t S = sb + (c & 1) * BUF1;
        const int kb = k0 + c * 128;
#pragma unroll
        for (int i = 0; i < 4; i++) {
            int idx = i * 512 + tid;
            int row = idx >> 4, cg = idx & 15;
            size_t g = (size_t)(n0 + row) * K + kb + cg * 8;
            cpa16(S + (row * PITCH + cg * 8) * 2, W + g);
        }
#pragma unroll
        for (int i = 0; i < 2; i++) {
            int idx = i * 512 + tid;
            int row = idx >> 4, cg = idx & 15;
            size_t g = (size_t)row * ldz + kb + cg * 8;
            cpa16(S + WBYTES + (row * PITCH + cg * 8) * 2, Z + g);
        }
        CP_COMMIT();
    };

    stage(0);
    for (int c = 0; c < chunks; c++) {
        if (c + 1 < chunks) {
            stage(c + 1);
            asm volatile("cp.async.wait_group 1;" ::: "memory");
        } else {
            asm volatile("cp.async.wait_group 0;" ::: "memory");
        }
        __syncthreads();

        const uint32_t S = sb + (c & 1) * BUF1;
        const uint32_t aw = S + ((wm * 32 + (lane & 15)) * PITCH + (lane >> 4) * 8) * 2;
        const uint32_t bz = S + WBYTES + ((wn * 16 + (lane & 15)) * PITCH + (lane >> 4) * 8) * 2;

#pragma unroll
        for (int ks = 0; ks < 8; ks++) {
            const uint32_t koff = ks * 32;
            uint32_t ah[2][4], bh[4];
#pragma unroll
            for (int mi = 0; mi < 2; mi++)
                ldm4(ah[mi], aw + mi * 16 * PITCH * 2 + koff);
            ldm4(bh, bz + koff);
#pragma unroll
            for (int mi = 0; mi < 2; mi++)
#pragma unroll
                for (int nj = 0; nj < 2; nj++)
                    mma_f16(acc[mi][nj], ah[mi], bh[nj], bh[2 + nj]);
        }
        __syncthreads();
    }

#pragma unroll
    for (int mi = 0; mi < 2; mi++)
#pragma unroll
        for (int nj = 0; nj < 2; nj++) {
            int m = n0 + wm * 32 + mi * 16 + (lane >> 2);
            int b = wn * 16 + nj * 8 + (lane & 3) * 2;
            if (!OUTH) {
                float* out = (float*)outv;
                __stcs((float2*)(out + (size_t)m * strideM + b),
                       make_float2(acc[mi][nj][0], acc[mi][nj][1]));
                __stcs((float2*)(out + (size_t)(m + 8) * strideM + b),
                       make_float2(acc[mi][nj][2], acc[mi][nj][3]));
            } else {
                __half* out = (__half*)outv;
                if (strideB == 1) {
                    *(__half2*)(out + (size_t)m * strideM + b) =
                        __floats2half2_rn(acc[mi][nj][0], acc[mi][nj][1]);
                    *(__half2*)(out + (size_t)(m + 8) * strideM + b) =
                        __floats2half2_rn(acc[mi][nj][2], acc[mi][nj][3]);
                } else {
                    out[(size_t)m * strideM + (size_t)b * strideB]             = __float2half_rn(acc[mi][nj][0]);
                    out[(size_t)m * strideM + (size_t)(b + 1) * strideB]       = __float2half_rn(acc[mi][nj][1]);
                    out[(size_t)(m + 8) * strideM + (size_t)b * strideB]       = __float2half_rn(acc[mi][nj][2]);
                    out[(size_t)(m + 8) * strideM + (size_t)(b + 1) * strideB] = __float2half_rn(acc[mi][nj][3]);
                }
            }
        }
}

// ---------------- fused cell: CTA (mt, ksl) handles dl in [ksl*8, ksl*8+8) ----------------
__device__ __forceinline__ void fused_cell(
    int mt, int ksl, const __half* __restrict__ base, const float* __restrict__ bias,
    float* __restrict__ cT,
    __half* hA, int offA, __half* hB, int offB,
    float* __restrict__ h1f)
{
    const int tid = threadIdx.x;
    const int dl = ksl * 8 + (tid >> 6);   // 0..31
    const int b  = tid & 63;
    const int d  = mt * 32 + dl;
    const int rbase = mt * 128 + dl * 4;   // n' row of gate 0
    float g[4];
#pragma unroll
    for (int j = 0; j < 4; j++) {
        size_t off = (size_t)(rbase + j) * 64 + b;
        float acc = bias[rbase + j];
        if (base) acc += __half2float(base[off]);
#pragma unroll
        for (int sl = 0; sl < 4; sl++)
            acc += __ldcs(g_part + (size_t)sl * 262144 + off);
        g[j] = acc;
    }
    float ig = 1.f / (1.f + expf(-g[0]));
    float fg = 1.f / (1.f + expf(-g[1]));
    float gg = tanhf(g[2]);
    float og = 1.f / (1.f + expf(-g[3]));
    float cn = fg * cT[d * 64 + b] + ig * gg;
    float h  = og * tanhf(cn);
    cT[d * 64 + b] = cn;
    __half hv = __float2half_rn(h);
    hA[b * 2048 + offA + d] = hv;
    hB[b * 2048 + offB + d] = hv;
    if (h1f) h1f[b * 1024 + d] = h;
}

// ---------------- persistent kernel ----------------
__global__ void __launch_bounds__(512) persistent_k(
    float* __restrict__ outs, float* __restrict__ attns)
{
    extern __shared__ __align__(16) char dsm[];
    const int bi = blockIdx.x, tid = threadIdx.x;
    const int lane = tid & 31, w = tid >> 5;
    const int mt = bi >> 2, ksl = bi & 3;
    int tgt = g_release;
    int mtgt = 0;

    for (int t = 0; t < 64; t++) {
        // ---- P1: LSTM0 GEMM (rows n') + fused cell0 ----
        gemm1<false>(g_Wc0H, g_Z0f, 2048,
                     g_part + (size_t)ksl * 262144, 64, 1,
                     2048, mt * 128, ksl * 512, 4, dsm);
        msync(mt, mtgt);
        fused_cell(mt, ksl, g_embWh + (size_t)t * 262144, g_bias0,
                   g_cT0, g_Z1f, 0, g_Z0f, 1024, nullptr);
        gsync(tgt, bi);
        // ---- P3: LSTM1 GEMM + fused cell1 (emits fp32 h1) ----
        gemm1<false>(g_Wc1H, g_Z1f, 2048,
                     g_part + (size_t)ksl * 262144, 64, 1,
                     2048, mt * 128, ksl * 512, 4, dsm);
        msync(mt, mtgt);
        fused_cell(mt, ksl, nullptr, g_bias1,
                   g_cT1, g_Z1f, 1024, g_Z1f, 1024, g_h1f);
        gsync(tgt, bi);
        // ---- P5: CTAs 0-63 scores+softmax; CTAs 64-127 out-GEMM (h1 half) ----
        if (bi < 64) {
            const int b = bi;
            float* qs = (float*)dsm;          // 1024 fp32 h1[b]
            float* sc = qs + 1024;            // 64 scores
            for (int d = tid; d < 1024; d += 512) qs[d] = g_h1f[b * 1024 + d];
            __syncthreads();
            const int bpair = b >> 1, brow = (b & 1) * 64;
#pragma unroll
            for (int so = 0; so < 4; so++) {
                int s = w * 4 + so;
                float acc = 0.f;
#pragma unroll
                for (int eblk = 0; eblk < 16; eblk++) {
                    const __half2* cwp = (const __half2*)(g_ctxWTh +
                        ((size_t)(bpair * 16 + eblk) * 128 + brow + s) * 64);
                    float2 cf = __half22float2(cwp[lane]);
                    float2 q2 = *(const float2*)(qs + eblk * 64 + 2 * lane);
                    acc += q2.x * cf.x + q2.y * cf.y;
                }
#pragma unroll
                for (int off = 16; off; off >>= 1)
                    acc += __shfl_down_sync(0xffffffffu, acc, off);
                if (lane == 0) sc[s] = acc;
            }
            __syncthreads();
            if (tid < 32) {
                float v0 = sc[tid], v1 = sc[tid + 32];
                float m = fmaxf(v0, v1);
#pragma unroll
                for (int off = 16; off; off >>= 1)
                    m = fmaxf(m, __shfl_xor_sync(0xffffffffu, m, off));
                float e0 = expf(v0 - m), e1 = expf(v1 - m);
                float s = e0 + e1;
#pragma unroll
                for (int off = 16; off; off >>= 1)
                    s += __shfl_xor_sync(0xffffffffu, s, off);
                float inv = 1.f / s;
                float a0 = e0 * inv, a1 = e1 * inv;
                g_align[b * 64 + tid] = a0;
                g_align[b * 64 + tid + 32] = a1;
                float* at = attns + (size_t)t * 4096 + b * 64;
                __stcs(at + tid, a0);
                __stcs(at + tid + 32, a1);
            }
        } else {
            const int idx = bi - 64;                  // 0..63
            const int om = idx >> 3, oks = idx & 7;   // 8 mtiles x 8 ksplits, 1 chunk
            gemm1<false>(g_WoutF, g_Z1f, 2048,
                         g_part + (size_t)(16 + oks) * 65536, 64, 1,
                         2048, om * 128, 1024 + oks * 128, 1, dsm);
        }
        gsync(tgt, bi);
        // ---- P6: combine: y = sum_s align*ctxOutH + sum_ks part; tanh; outputs+feed ----
        {
            float* salign = (float*)dsm;   // 64*64
            for (int i = tid; i < 4096; i += 512) salign[i] = g_align[i];
            __syncthreads();
            int e = bi * 512 + tid;
            int n = e >> 6, b = e & 63;
            float acc = 0.f;
#pragma unroll
            for (int ks = 0; ks < 8; ks++)
                acc += __ldcs(g_part + (size_t)(16 + ks) * 65536 + e);
            const uint4* co = (const uint4*)(g_ctxOutH + (size_t)e * 64);
            const float* al = salign + b * 64;
#pragma unroll
            for (int sq = 0; sq < 8; sq++) {       // 8 x uint4 = 64 halfs
                uint4 u = co[sq];
                float2 v0 = __half22float2(*(const __half2*)&u.x);
                float2 v1 = __half22float2(*(const __half2*)&u.y);
                float2 v2 = __half22float2(*(const __half2*)&u.z);
                float2 v3 = __half22float2(*(const __half2*)&u.w);
                const float* a8 = al + sq * 8;
                acc += a8[0] * v0.x + a8[1] * v0.y + a8[2] * v1.x + a8[3] * v1.y
                     + a8[4] * v2.x + a8[5] * v2.y + a8[6] * v3.x + a8[7] * v3.y;
            }
            float h = tanhf(acc);
            __stcs(outs + (size_t)t * 65536 + b * 1024 + n, h);
            g_Z0f[b * 2048 + n] = __float2half_rn(h);
        }
        gsync(tgt, bi);
    }

    // reset mini counters for next graph replay (all CTAs past all msyncs here)
    if (ksl == 0 && tid == 0) g_mcnt[mt] = 0;
}

// ---------------- embW precompute: [t][n'][b] = emb_t @ W0e^T (fp16 out) ----------------
__global__ void __launch_bounds__(512) gemm_pre()
{
    extern __shared__ __align__(16) char dsm[];
    gemm1<true>(g_W0eH, g_embH + (size_t)blockIdx.y * 65536, 1024,
                g_embWh + (size_t)blockIdx.y * 262144, 64, 1,
                1024, blockIdx.x * 128, 0, 8, dsm);
}

// ---------------- ctxW precompute: scores matrix (fp16) ----------------
__global__ void __launch_bounds__(512) ctxw_pre()
{
    extern __shared__ __align__(16) char dsm[];
    const int bpair = blockIdx.x;   // 32
    const int eblk  = blockIdx.y;   // 16
    gemm1<true>(g_ctxRf + (size_t)bpair * 131072,
                g_WinTf + (size_t)eblk * 65536, 1024,
                g_ctxWTh + ((size_t)bpair * 16 + eblk) * 8192, 64, 1,
                1024, 0, 0, 8, dsm);
}

// ---------------- ctxOut precompute: [(n*64+b)][s] = Wout_cvec . ctx[s,b] (fp16) ----------------
__global__ void __launch_bounds__(512) ctxout_pre()
{
    extern __shared__ __align__(16) char dsm[];
    const int mt = blockIdx.x;   // 8
    const int s  = blockIdx.y;   // 64
    gemm1<true>(g_WoutF, g_ctxPf + (size_t)s * 65536, 1024,
                g_ctxOutH + s, 4096, 64,
                2048, mt * 128, 0, 8, dsm);
}

// ---------------- init state ----------------
__global__ void init_state(const float* __restrict__ input_feed,
                           const float* __restrict__ h0, const float* __restrict__ c0)
{
    int e = blockIdx.x * blockDim.x + threadIdx.x;  // 65536
    int b = e >> 10, d = e & 1023;
    g_Z0f[b * 2048 + d] = __float2half_rn(input_feed[e]);
    g_Z0f[b * 2048 + 1024 + d] = __float2half_rn(h0[e]);
    g_Z1f[b * 2048 + 1024 + d] = __float2half_rn(h0[65536 + e]);
    g_cT0[d * 64 + b] = c0[e];
    g_cT1[d * 64 + b] = c0[65536 + e];
}

// ---------------- weight prep (gate-interleaved rows n' = d*4 + gate) ----------------
__global__ void prep_w(const float* __restrict__ W_ih0, const float* __restrict__ W_hh0,
                       const float* __restrict__ W_ih1, const float* __restrict__ W_hh1,
                       const float* __restrict__ W_in,  const float* __restrict__ W_out,
                       const float* __restrict__ emb,   const float* __restrict__ ctx,
                       const float* __restrict__ b_ih0, const float* __restrict__ b_hh0,
                       const float* __restrict__ b_ih1, const float* __restrict__ b_hh1)
{
    size_t stride = (size_t)gridDim.x * blockDim.x;
    for (size_t i = (size_t)blockIdx.x * blockDim.x + threadIdx.x;
         i < 4096ull * 2048ull; i += stride) {
        size_t n = i >> 11, k = i & 2047;
        size_t np = (n & 1023) * 4 + (n >> 10);
        float v0 = (k < 1024) ? W_ih0[n * 2048 + 1024 + k] : W_hh0[n * 1024 + (k - 1024)];
        g_Wc0H[np * 2048 + k] = __float2half_rn(v0);
        float v1 = (k < 1024) ? W_ih1[n * 1024 + k] : W_hh1[n * 1024 + (k - 1024)];
        g_Wc1H[np * 2048 + k] = __float2half_rn(v1);
        if (n < 1024) g_WoutF[i] = __float2half_rn(W_out[i]);
        if (i < 4096ull * 1024ull) {
            size_t nn = i >> 10, kk = i & 1023;
            size_t np2 = (nn & 1023) * 4 + (nn >> 10);
            g_W0eH[np2 * 1024 + kk] = __float2half_rn(W_ih0[nn * 2048 + kk]);
            g_embH[i] = __float2half_rn(emb[i]);
            g_ctxPf[i] = __float2half_rn(ctx[i]);
            size_t b = (i >> 10) & 63, s = i >> 16, d = i & 1023;
            size_t ri = ((b >> 1) * 128 + (b & 1) * 64 + s) * 1024 + d;
            g_ctxRf[ri] = __float2half_rn(ctx[i]);
        }
        if (i < 1024ull * 1024ull) {
            size_t ti = (i & 1023) * 1024 + (i >> 10);
            g_WinTf[ti] = __float2half_rn(W_in[i]);
        }
        if (i < 4096) {
            size_t np3 = (i & 1023) * 4 + (i >> 10);
            g_bias0[np3] = b_ih0[i] + b_hh0[i];
            g_bias1[np3] = b_ih1[i] + b_hh1[i];
        }
    }
}

// ---------------- host orchestration ----------------
extern "C" void kernel_launch(void* const* d_in, const int* in_sizes, int n_in,
                              void* d_out, int out_size)
{
    (void)in_sizes; (void)n_in; (void)out_size;
    const float* emb        = (const float*)d_in[0];
    const float* context    = (const float*)d_in[1];
    const float* input_feed = (const float*)d_in[2];
    const float* h0         = (const float*)d_in[3];
    const float* c0         = (const float*)d_in[4];
    const float* W_ih0      = (const float*)d_in[5];
    const float* W_hh0      = (const float*)d_in[6];
    const float* b_ih0      = (const float*)d_in[7];
    const float* b_hh0      = (const float*)d_in[8];
    const float* W_ih1      = (const float*)d_in[9];
    const float* W_hh1      = (const float*)d_in[10];
    const float* b_ih1      = (const float*)d_in[11];
    const float* b_hh1      = (const float*)d_in[12];
    const float* W_in       = (const float*)d_in[13];
    const float* W_out      = (const float*)d_in[14];

    float* outs  = (float*)d_out;
    float* attns = outs + 64 * 64 * 1024;

    static bool attr_set = false;
    if (!attr_set) {
        cudaFuncSetAttribute(persistent_k, cudaFuncAttributeMaxDynamicSharedMemorySize, GEMM_SMEM);
        cudaFuncSetAttribute(gemm_pre, cudaFuncAttributeMaxDynamicSharedMemorySize, GEMM_SMEM);
        cudaFuncSetAttribute(ctxw_pre, cudaFuncAttributeMaxDynamicSharedMemorySize, GEMM_SMEM);
        cudaFuncSetAttribute(ctxout_pre, cudaFuncAttributeMaxDynamicSharedMemorySize, GEMM_SMEM);
        attr_set = true;
    }

    prep_w<<<4096, 256>>>(W_ih0, W_hh0, W_ih1, W_hh1, W_in, W_out, emb, context,
                          b_ih0, b_hh0, b_ih1, b_hh1);
    init_state<<<256, 256>>>(input_feed, h0, c0);
    ctxw_pre<<<dim3(32, 16), 512, GEMM_SMEM>>>();
    ctxout_pre<<<dim3(8, 64), 512, GEMM_SMEM>>>();
    gemm_pre<<<dim3(32, 64), 512, GEMM_SMEM>>>();
    persistent_k<<<NCTA, 512, GEMM_SMEM>>>(outs, attns);
}

// round 17
// speedup vs baseline: 1.8598x; 1.0198x over previous
#include <cuda_runtime.h>
#include <cuda_fp16.h>
#include <cstdint>
#include <math.h>

// Shapes: T=64, B=64, S=64, E=1024, D=1024, G=4096
// Persistent kernel: 128 CTAs x 512 threads, one CTA per SM.
// ALL GEMMs single-term fp16 (mma.sync m16n8k16 f16->f32).
// Gate-interleaved weight rows (n' = d*4 + gate); LSTM cells fused into GEMM phases
// behind 4-CTA mini-barriers: 4 phases + 4 global barriers/step.
// Prep: single merged kernel (ctxW scores + coalesced ctxOut + embW).

#define NCTA 128

// ---------------- static device scratch ----------------
__device__ __align__(16) __half g_W0eH[4096*1024];   // W_ih0[:, :1024], rows n'
__device__ __align__(16) __half g_Wc0H[4096*2048];   // [W_ih0[:,1024:] | W_hh0], rows n'
__device__ __align__(16) __half g_Wc1H[4096*2048];   // [W_ih1 | W_hh1], rows n'
__device__ __align__(16) __half g_WoutF[1024*2048];  // full W_out (natural rows)
__device__ __align__(16) __half g_embH[4096*1024];   // emb rows (t*64+b)
__device__ __align__(16) __half g_ctxRf[4096*1024];  // ctx repacked per bpair
__device__ __align__(16) __half g_ctxPf[4096*1024];  // ctx plain [(s*64+b)][d]
__device__ __align__(16) __half g_WinTf[1024*1024];  // W_in^T: [e][d]
__device__ __align__(16) __half g_ctxWTh[64*64*1024];// [(bpair*16+eblk)][srow(128)][elocal(64)]
__device__ __align__(16) __half g_ctxOutH[1024*64*64];// [(n*64+b)][s]
__device__ __align__(16) __half g_embWh[64*4096*64]; // [t][n'][b]
__device__ __align__(16) float g_part[24*1024*64];   // split-K partials
__device__ __align__(16) __half g_Z0f[64*2048];      // [feed | h0_prev]
__device__ __align__(16) __half g_Z1f[64*2048];      // [h0_new | h1]
__device__ __align__(16) float g_h1f[64*1024];       // fp32 h1 [b][d]
__device__ __align__(16) float g_align[64*64];       // align [b][s]
__device__ __align__(16) float g_cT0[1024*64], g_cT1[1024*64];
__device__ __align__(16) float g_bias0[4096], g_bias1[4096];  // reordered n'
__device__ volatile int g_arrive[NCTA];
__device__ volatile int g_release;
__device__ int g_mcnt[32];                           // per-mtile mini counters

// ---------------- PTX helpers ----------------
__device__ __forceinline__ uint32_t smem_u32(const void* p) {
    uint32_t a;
    asm("{ .reg .u64 t; cvta.to.shared.u64 t, %1; cvt.u32.u64 %0, t; }" : "=r"(a) : "l"(p));
    return a;
}
__device__ __forceinline__ void ldm4(uint32_t* r, uint32_t a) {
    asm volatile("ldmatrix.sync.aligned.m8n8.x4.shared.b16 {%0,%1,%2,%3}, [%4];"
                 : "=r"(r[0]), "=r"(r[1]), "=r"(r[2]), "=r"(r[3]) : "r"(a));
}
__device__ __forceinline__ void mma_f16(float* c, const uint32_t* a, uint32_t b0, uint32_t b1) {
    asm volatile("mma.sync.aligned.m16n8k16.row.col.f32.f16.f16.f32 "
                 "{%0,%1,%2,%3}, {%4,%5,%6,%7}, {%8,%9}, {%0,%1,%2,%3};"
                 : "+f"(c[0]), "+f"(c[1]), "+f"(c[2]), "+f"(c[3])
                 : "r"(a[0]), "r"(a[1]), "r"(a[2]), "r"(a[3]), "r"(b0), "r"(b1));
}
__device__ __forceinline__ void cpa16(uint32_t s, const void* g) {
    asm volatile("cp.async.cg.shared.global [%0], [%1], 16;" :: "r"(s), "l"(g));
}
#define CP_COMMIT() asm volatile("cp.async.commit_group;" ::: "memory")

// fast global barrier: per-CTA arrive flags + CTA0 scan + release word
__device__ __forceinline__ void gsync(int& tgt, int bi) {
    __syncthreads();
    tgt++;
    if (threadIdx.x == 0) { __threadfence(); g_arrive[bi] = tgt; }
    if (bi == 0) {
        if (threadIdx.x < NCTA) {
            while (g_arrive[threadIdx.x] - tgt < 0) {}
        }
        __syncthreads();
        if (threadIdx.x == 0) { __threadfence(); g_release = tgt; }
    } else {
        if (threadIdx.x == 0) {
            while (g_release - tgt < 0) {}
            __threadfence();
        }
    }
    __syncthreads();
}

// 4-CTA mini-barrier per mtile (monotonic counter; reset at kernel end)
__device__ __forceinline__ void msync(int mt, int& mtgt) {
    __syncthreads();
    mtgt += 4;
    if (threadIdx.x == 0) {
        __threadfence();
        atomicAdd(&g_mcnt[mt], 1);
        while (*(volatile int*)&g_mcnt[mt] - mtgt < 0) {}
        __threadfence();
    }
    __syncthreads();
}

// ---------------- tile constants (Kchunk=128) ----------------
static constexpr int PITCH = 136;                   // 16-bit elems; 272B rows
static constexpr int WBYTES = 128 * PITCH * 2;      // 34816
static constexpr int ZBYTES = 64 * PITCH * 2;       // 17408
static constexpr int BUF1 = WBYTES + ZBYTES;        // 52224
static constexpr int GEMM_SMEM = 2 * BUF1;          // 104448

// ---------------- fp16 single-term GEMM tile (512 threads, 4x4 warp grid) ----------------
template <bool OUTH>
__device__ __forceinline__ void gemm1(
    const __half* __restrict__ W,
    const __half* __restrict__ Z, int ldz,
    void* __restrict__ outv, size_t strideM, int strideB,
    int K, int n0, int k0, int chunks, char* dsm)
{
    const int tid  = threadIdx.x;
    const int lane = tid & 31, wid = tid >> 5;
    const int wm = wid >> 2, wn = wid & 3;
    const uint32_t sb = smem_u32(dsm);

    float acc[2][2][4];
#pragma unroll
    for (int mi = 0; mi < 2; mi++)
#pragma unroll
        for (int nj = 0; nj < 2; nj++)
#pragma unroll
            for (int q = 0; q < 4; q++) acc[mi][nj][q] = 0.f;

    auto stage = [&](int c) {
        const uint32_t S = sb + (c & 1) * BUF1;
        const int kb = k0 + c * 128;
#pragma unroll
        for (int i = 0; i < 4; i++) {
            int idx = i * 512 + tid;
            int row = idx >> 4, cg = idx & 15;
            size_t g = (size_t)(n0 + row) * K + kb + cg * 8;
            cpa16(S + (row * PITCH + cg * 8) * 2, W + g);
        }
#pragma unroll
        for (int i = 0; i < 2; i++) {
            int idx = i * 512 + tid;
            int row = idx >> 4, cg = idx & 15;
            size_t g = (size_t)row * ldz + kb + cg * 8;
            cpa16(S + WBYTES + (row * PITCH + cg * 8) * 2, Z + g);
        }
        CP_COMMIT();
    };

    stage(0);
    for (int c = 0; c < chunks; c++) {
        if (c + 1 < chunks) {
            stage(c + 1);
            asm volatile("cp.async.wait_group 1;" ::: "memory");
        } else {
            asm volatile("cp.async.wait_group 0;" ::: "memory");
        }
        __syncthreads();

        const uint32_t S = sb + (c & 1) * BUF1;
        const uint32_t aw = S + ((wm * 32 + (lane & 15)) * PITCH + (lane >> 4) * 8) * 2;
        const uint32_t bz = S + WBYTES + ((wn * 16 + (lane & 15)) * PITCH + (lane >> 4) * 8) * 2;

#pragma unroll
        for (int ks = 0; ks < 8; ks++) {
            const uint32_t koff = ks * 32;
            uint32_t ah[2][4], bh[4];
#pragma unroll
            for (int mi = 0; mi < 2; mi++)
                ldm4(ah[mi], aw + mi * 16 * PITCH * 2 + koff);
            ldm4(bh, bz + koff);
#pragma unroll
            for (int mi = 0; mi < 2; mi++)
#pragma unroll
                for (int nj = 0; nj < 2; nj++)
                    mma_f16(acc[mi][nj], ah[mi], bh[nj], bh[2 + nj]);
        }
        __syncthreads();
    }

#pragma unroll
    for (int mi = 0; mi < 2; mi++)
#pragma unroll
        for (int nj = 0; nj < 2; nj++) {
            int m = n0 + wm * 32 + mi * 16 + (lane >> 2);
            int b = wn * 16 + nj * 8 + (lane & 3) * 2;
            if (!OUTH) {
                float* out = (float*)outv;
                __stcs((float2*)(out + (size_t)m * strideM + b),
                       make_float2(acc[mi][nj][0], acc[mi][nj][1]));
                __stcs((float2*)(out + (size_t)(m + 8) * strideM + b),
                       make_float2(acc[mi][nj][2], acc[mi][nj][3]));
            } else {
                __half* out = (__half*)outv;
                if (strideB == 1) {
                    *(__half2*)(out + (size_t)m * strideM + b) =
                        __floats2half2_rn(acc[mi][nj][0], acc[mi][nj][1]);
                    *(__half2*)(out + (size_t)(m + 8) * strideM + b) =
                        __floats2half2_rn(acc[mi][nj][2], acc[mi][nj][3]);
                } else {
                    out[(size_t)m * strideM + (size_t)b * strideB]             = __float2half_rn(acc[mi][nj][0]);
                    out[(size_t)m * strideM + (size_t)(b + 1) * strideB]       = __float2half_rn(acc[mi][nj][1]);
                    out[(size_t)(m + 8) * strideM + (size_t)b * strideB]       = __float2half_rn(acc[mi][nj][2]);
                    out[(size_t)(m + 8) * strideM + (size_t)(b + 1) * strideB] = __float2half_rn(acc[mi][nj][3]);
                }
            }
        }
}

// ---------------- fused cell: CTA (mt, ksl) handles dl in [ksl*8, ksl*8+8) ----------------
__device__ __forceinline__ void fused_cell(
    int mt, int ksl, const __half* __restrict__ base, const float* __restrict__ bias,
    float* __restrict__ cT,
    __half* hA, int offA, __half* hB, int offB,
    float* __restrict__ h1f)
{
    const int tid = threadIdx.x;
    const int dl = ksl * 8 + (tid >> 6);   // 0..31
    const int b  = tid & 63;
    const int d  = mt * 32 + dl;
    const int rbase = mt * 128 + dl * 4;   // n' row of gate 0
    float g[4];
#pragma unroll
    for (int j = 0; j < 4; j++) {
        size_t off = (size_t)(rbase + j) * 64 + b;
        float acc = bias[rbase + j];
        if (base) acc += __half2float(base[off]);
#pragma unroll
        for (int sl = 0; sl < 4; sl++)
            acc += __ldcs(g_part + (size_t)sl * 262144 + off);
        g[j] = acc;
    }
    float ig = 1.f / (1.f + expf(-g[0]));
    float fg = 1.f / (1.f + expf(-g[1]));
    float gg = tanhf(g[2]);
    float og = 1.f / (1.f + expf(-g[3]));
    float cn = fg * cT[d * 64 + b] + ig * gg;
    float h  = og * tanhf(cn);
    cT[d * 64 + b] = cn;
    __half hv = __float2half_rn(h);
    hA[b * 2048 + offA + d] = hv;
    hB[b * 2048 + offB + d] = hv;
    if (h1f) h1f[b * 1024 + d] = h;
}

// ---------------- persistent kernel ----------------
__global__ void __launch_bounds__(512) persistent_k(
    float* __restrict__ outs, float* __restrict__ attns)
{
    extern __shared__ __align__(16) char dsm[];
    const int bi = blockIdx.x, tid = threadIdx.x;
    const int lane = tid & 31, w = tid >> 5;
    const int mt = bi >> 2, ksl = bi & 3;
    int tgt = g_release;
    int mtgt = 0;

    for (int t = 0; t < 64; t++) {
        // ---- P1: LSTM0 GEMM (rows n') + fused cell0 ----
        gemm1<false>(g_Wc0H, g_Z0f, 2048,
                     g_part + (size_t)ksl * 262144, 64, 1,
                     2048, mt * 128, ksl * 512, 4, dsm);
        msync(mt, mtgt);
        fused_cell(mt, ksl, g_embWh + (size_t)t * 262144, g_bias0,
                   g_cT0, g_Z1f, 0, g_Z0f, 1024, nullptr);
        gsync(tgt, bi);
        // ---- P3: LSTM1 GEMM + fused cell1 (emits fp32 h1) ----
        gemm1<false>(g_Wc1H, g_Z1f, 2048,
                     g_part + (size_t)ksl * 262144, 64, 1,
                     2048, mt * 128, ksl * 512, 4, dsm);
        msync(mt, mtgt);
        fused_cell(mt, ksl, nullptr, g_bias1,
                   g_cT1, g_Z1f, 1024, g_Z1f, 1024, g_h1f);
        gsync(tgt, bi);
        // ---- P5: CTAs 0-63 scores+softmax; CTAs 64-127 out-GEMM (h1 half) ----
        if (bi < 64) {
            const int b = bi;
            float* qs = (float*)dsm;          // 1024 fp32 h1[b]
            float* sc = qs + 1024;            // 64 scores
            for (int d = tid; d < 1024; d += 512) qs[d] = g_h1f[b * 1024 + d];
            __syncthreads();
            const int bpair = b >> 1, brow = (b & 1) * 64;
#pragma unroll
            for (int so = 0; so < 4; so++) {
                int s = w * 4 + so;
                float acc = 0.f;
#pragma unroll
                for (int eblk = 0; eblk < 16; eblk++) {
                    const __half2* cwp = (const __half2*)(g_ctxWTh +
                        ((size_t)(bpair * 16 + eblk) * 128 + brow + s) * 64);
                    float2 cf = __half22float2(cwp[lane]);
                    float2 q2 = *(const float2*)(qs + eblk * 64 + 2 * lane);
                    acc += q2.x * cf.x + q2.y * cf.y;
                }
#pragma unroll
                for (int off = 16; off; off >>= 1)
                    acc += __shfl_down_sync(0xffffffffu, acc, off);
                if (lane == 0) sc[s] = acc;
            }
            __syncthreads();
            if (tid < 32) {
                float v0 = sc[tid], v1 = sc[tid + 32];
                float m = fmaxf(v0, v1);
#pragma unroll
                for (int off = 16; off; off >>= 1)
                    m = fmaxf(m, __shfl_xor_sync(0xffffffffu, m, off));
                float e0 = expf(v0 - m), e1 = expf(v1 - m);
                float s = e0 + e1;
#pragma unroll
                for (int off = 16; off; off >>= 1)
                    s += __shfl_xor_sync(0xffffffffu, s, off);
                float inv = 1.f / s;
                float a0 = e0 * inv, a1 = e1 * inv;
                g_align[b * 64 + tid] = a0;
                g_align[b * 64 + tid + 32] = a1;
                float* at = attns + (size_t)t * 4096 + b * 64;
                __stcs(at + tid, a0);
                __stcs(at + tid + 32, a1);
            }
        } else {
            const int idx = bi - 64;                  // 0..63
            const int om = idx >> 3, oks = idx & 7;   // 8 mtiles x 8 ksplits, 1 chunk
            gemm1<false>(g_WoutF, g_Z1f, 2048,
                         g_part + (size_t)(16 + oks) * 65536, 64, 1,
                         2048, om * 128, 1024 + oks * 128, 1, dsm);
        }
        gsync(tgt, bi);
        // ---- P6: combine: y = sum_s align*ctxOutH + sum_ks part; tanh; outputs+feed ----
        {
            float* salign = (float*)dsm;   // 64*64
            for (int i = tid; i < 4096; i += 512) salign[i] = g_align[i];
            __syncthreads();
            int e = bi * 512 + tid;
            int n = e >> 6, b = e & 63;
            float acc = 0.f;
#pragma unroll
            for (int ks = 0; ks < 8; ks++)
                acc += __ldcs(g_part + (size_t)(16 + ks) * 65536 + e);
            const uint4* co = (const uint4*)(g_ctxOutH + (size_t)e * 64);
            const float* al = salign + b * 64;
#pragma unroll
            for (int sq = 0; sq < 8; sq++) {       // 8 x uint4 = 64 halfs
                uint4 u = co[sq];
                float2 v0 = __half22float2(*(const __half2*)&u.x);
                float2 v1 = __half22float2(*(const __half2*)&u.y);
                float2 v2 = __half22float2(*(const __half2*)&u.z);
                float2 v3 = __half22float2(*(const __half2*)&u.w);
                const float* a8 = al + sq * 8;
                acc += a8[0] * v0.x + a8[1] * v0.y + a8[2] * v1.x + a8[3] * v1.y
                     + a8[4] * v2.x + a8[5] * v2.y + a8[6] * v3.x + a8[7] * v3.y;
            }
            float h = tanhf(acc);
            __stcs(outs + (size_t)t * 65536 + b * 1024 + n, h);
            g_Z0f[b * 2048 + n] = __float2half_rn(h);
        }
        gsync(tgt, bi);
    }

    // reset mini counters for next graph replay (all CTAs past all msyncs here)
    if (ksl == 0 && tid == 0) g_mcnt[mt] = 0;
}

// ---------------- merged prep: ctxW (512) + coalesced ctxOut (512) + embW (2048) ----------------
__global__ void __launch_bounds__(512) pre_all()
{
    extern __shared__ __align__(16) char dsm[];
    const int bi = blockIdx.x;
    if (bi < 512) {
        // ctxW scores matrix: [(bpair*16+eblk)][srow(128)][elocal(64)]
        const int bpair = bi >> 4, eblk = bi & 15;
        gemm1<true>(g_ctxRf + (size_t)bpair * 131072,
                    g_WinTf + (size_t)eblk * 65536, 1024,
                    g_ctxWTh + ((size_t)bpair * 16 + eblk) * 8192, 64, 1,
                    1024, 0, 0, 8, dsm);
    } else if (bi < 1024) {
        // ctxOut: per-batch GEMM, N = s -> coalesced half2 stores.
        // ctxOut[(n*64+b)][s] = Wout[n, :1024] . ctx[s,b,:]
        const int idx = bi - 512;
        const int mt = idx >> 6, b = idx & 63;    // 8 mtiles x 64 batches
        gemm1<true>(g_WoutF,
                    g_ctxPf + (size_t)b * 1024, 65536,
                    g_ctxOutH + (size_t)b * 64, 4096, 1,
                    2048, mt * 128, 0, 8, dsm);
    } else {
        // embW: [t][n'][b] = emb_t @ W0e^T
        const int idx = bi - 1024;
        const int mt = idx & 31, t = idx >> 5;    // 32 mtiles x 64 t
        gemm1<true>(g_W0eH, g_embH + (size_t)t * 65536, 1024,
                    g_embWh + (size_t)t * 262144, 64, 1,
                    1024, mt * 128, 0, 8, dsm);
    }
}

// ---------------- init state ----------------
__global__ void init_state(const float* __restrict__ input_feed,
                           const float* __restrict__ h0, const float* __restrict__ c0)
{
    int e = blockIdx.x * blockDim.x + threadIdx.x;  // 65536
    int b = e >> 10, d = e & 1023;
    g_Z0f[b * 2048 + d] = __float2half_rn(input_feed[e]);
    g_Z0f[b * 2048 + 1024 + d] = __float2half_rn(h0[e]);
    g_Z1f[b * 2048 + 1024 + d] = __float2half_rn(h0[65536 + e]);
    g_cT0[d * 64 + b] = c0[e];
    g_cT1[d * 64 + b] = c0[65536 + e];
}

// ---------------- weight prep (gate-interleaved rows n' = d*4 + gate) ----------------
__global__ void prep_w(const float* __restrict__ W_ih0, const float* __restrict__ W_hh0,
                       const float* __restrict__ W_ih1, const float* __restrict__ W_hh1,
                       const float* __restrict__ W_in,  const float* __restrict__ W_out,
                       const float* __restrict__ emb,   const float* __restrict__ ctx,
                       const float* __restrict__ b_ih0, const float* __restrict__ b_hh0,
                       const float* __restrict__ b_ih1, const float* __restrict__ b_hh1)
{
    size_t stride = (size_t)gridDim.x * blockDim.x;
    for (size_t i = (size_t)blockIdx.x * blockDim.x + threadIdx.x;
         i < 4096ull * 2048ull; i += stride) {
        size_t n = i >> 11, k = i & 2047;
        size_t np = (n & 1023) * 4 + (n >> 10);
        float v0 = (k < 1024) ? W_ih0[n * 2048 + 1024 + k] : W_hh0[n * 1024 + (k - 1024)];
        g_Wc0H[np * 2048 + k] = __float2half_rn(v0);
        float v1 = (k < 1024) ? W_ih1[n * 1024 + k] : W_hh1[n * 1024 + (k - 1024)];
        g_Wc1H[np * 2048 + k] = __float2half_rn(v1);
        if (n < 1024) g_WoutF[i] = __float2half_rn(W_out[i]);
        if (i < 4096ull * 1024ull) {
            size_t nn = i >> 10, kk = i & 1023;
            size_t np2 = (nn & 1023) * 4 + (nn >> 10);
            g_W0eH[np2 * 1024 + kk] = __float2half_rn(W_ih0[nn * 2048 + kk]);
            g_embH[i] = __float2half_rn(emb[i]);
            g_ctxPf[i] = __float2half_rn(ctx[i]);
            size_t b = (i >> 10) & 63, s = i >> 16, d = i & 1023;
            size_t ri = ((b >> 1) * 128 + (b & 1) * 64 + s) * 1024 + d;
            g_ctxRf[ri] = __float2half_rn(ctx[i]);
        }
        if (i < 1024ull * 1024ull) {
            size_t ti = (i & 1023) * 1024 + (i >> 10);
            g_WinTf[ti] = __float2half_rn(W_in[i]);
        }
        if (i < 4096) {
            size_t np3 = (i & 1023) * 4 + (i >> 10);
            g_bias0[np3] = b_ih0[i] + b_hh0[i];
            g_bias1[np3] = b_ih1[i] + b_hh1[i];
        }
    }
}

// ---------------- host orchestration ----------------
extern "C" void kernel_launch(void* const* d_in, const int* in_sizes, int n_in,
                              void* d_out, int out_size)
{
    (void)in_sizes; (void)n_in; (void)out_size;
    const float* emb        = (const float*)d_in[0];
    const float* context    = (const float*)d_in[1];
    const float* input_feed = (const float*)d_in[2];
    const float* h0         = (const float*)d_in[3];
    const float* c0         = (const float*)d_in[4];
    const float* W_ih0      = (const float*)d_in[5];
    const float* W_hh0      = (const float*)d_in[6];
    const float* b_ih0      = (const float*)d_in[7];
    const float* b_hh0      = (const float*)d_in[8];
    const float* W_ih1      = (const float*)d_in[9];
    const float* W_hh1      = (const float*)d_in[10];
    const float* b_ih1      = (const float*)d_in[11];
    const float* b_hh1      = (const float*)d_in[12];
    const float* W_in       = (const float*)d_in[13];
    const float* W_out      = (const float*)d_in[14];

    float* outs  = (float*)d_out;
    float* attns = outs + 64 * 64 * 1024;

    static bool attr_set = false;
    if (!attr_set) {
        cudaFuncSetAttribute(persistent_k, cudaFuncAttributeMaxDynamicSharedMemorySize, GEMM_SMEM);
        cudaFuncSetAttribute(pre_all, cudaFuncAttributeMaxDynamicSharedMemorySize, GEMM_SMEM);
        attr_set = true;
    }

    prep_w<<<4096, 256>>>(W_ih0, W_hh0, W_ih1, W_hh1, W_in, W_out, emb, context,
                          b_ih0, b_hh0, b_ih1, b_hh1);
    init_state<<<256, 256>>>(input_feed, h0, c0);
    pre_all<<<3072, 512, GEMM_SMEM>>>();
    persistent_k<<<NCTA, 512, GEMM_SMEM>>>(outs, attns);
}